// round 4
// baseline (speedup 1.0000x reference)
#include <cuda_runtime.h>
#include <cuda_bf16.h>

#define N_NODES 50000
#define N_EDGES 800000
#define D 128
#define BN_BLOCKS 250
#define BN_ROWS 200

// -------- device scratch (no runtime allocation allowed) --------
__device__ int   g_cnt[N_NODES];          // zero-init; reset by scan each call
__device__ int   g_off[N_NODES + 1];
__device__ int   g_pos[N_NODES];
__device__ int   g_src_sorted[N_EDGES];
__device__ float g_mean[(size_t)N_NODES * D];
__device__ float g_h0[(size_t)N_NODES * D];
__device__ float g_h1[(size_t)N_NODES * D];
__device__ float g_part_s[BN_BLOCKS * D];
__device__ float g_part_s2[BN_BLOCKS * D];
__device__ float g_bn_scale[D];
__device__ float g_bn_shift[D];

// -------- CSR build --------
__global__ void hist_kernel(const int* __restrict__ dst) {
    int e = blockIdx.x * blockDim.x + threadIdx.x;
    if (e < N_EDGES) atomicAdd(&g_cnt[dst[e]], 1);
}

// single-block, tile-wise shuffle scan over 50000 counts; coalesced.
// Also resets g_cnt for the next replay.
__global__ void scan_kernel() {
    __shared__ int ws[32];
    const int t = threadIdx.x;        // 1024 threads
    const int lane = t & 31;
    const int warp = t >> 5;
    int base = 0;
    const int NT = (N_NODES + 1023) / 1024;  // 49
    for (int tile = 0; tile < NT; tile++) {
        int idx = tile * 1024 + t;
        int v = 0;
        if (idx < N_NODES) {
            v = g_cnt[idx];
            g_cnt[idx] = 0;  // reset for next graph replay
        }
        // warp inclusive scan
        int inc = v;
#pragma unroll
        for (int o = 1; o < 32; o <<= 1) {
            int u = __shfl_up_sync(0xffffffffu, inc, o);
            if (lane >= o) inc += u;
        }
        if (lane == 31) ws[warp] = inc;
        __syncthreads();
        if (warp == 0) {
            int wv = ws[lane];
            int winc = wv;
#pragma unroll
            for (int o = 1; o < 32; o <<= 1) {
                int u = __shfl_up_sync(0xffffffffu, winc, o);
                if (lane >= o) winc += u;
            }
            ws[lane] = winc - wv;  // exclusive warp offsets
        }
        __syncthreads();
        int excl = base + ws[warp] + inc - v;
        if (idx < N_NODES) {
            g_off[idx] = excl;
            g_pos[idx] = excl;
        }
        // tile total = ws[31] (exclusive of warp31) + inclusive sum of warp31
        int tile_total = __shfl_sync(0xffffffffu, excl + v, 31) - base;
        tile_total = __shfl_sync(0xffffffffu, tile_total, 31);
        // broadcast warp31's last value to all warps via smem
        __shared__ int tot_sh;
        if (t == 1023) tot_sh = excl + v - base;
        __syncthreads();
        base += tot_sh;
        __syncthreads();
    }
    if (t == 0) g_off[N_NODES] = base;
}

__global__ void scatter_kernel(const int* __restrict__ src,
                               const int* __restrict__ dst) {
    int e = blockIdx.x * blockDim.x + threadIdx.x;
    if (e < N_EDGES) {
        int p = atomicAdd(&g_pos[dst[e]], 1);
        g_src_sorted[p] = src[e];
    }
}

// -------- mean aggregation: one warp per node, lane = 4 feature floats --------
__global__ void agg_kernel(const float* __restrict__ h, float* __restrict__ out) {
    int gw = (blockIdx.x * blockDim.x + threadIdx.x) >> 5;
    int lane = threadIdx.x & 31;
    if (gw >= N_NODES) return;
    int beg = g_off[gw];
    int end = g_off[gw + 1];
    float4 acc0 = make_float4(0.f, 0.f, 0.f, 0.f);
    float4 acc1 = make_float4(0.f, 0.f, 0.f, 0.f);
    int i = beg;
    for (; i + 3 < end; i += 4) {
        int s0 = __ldg(&g_src_sorted[i]);
        int s1 = __ldg(&g_src_sorted[i + 1]);
        int s2 = __ldg(&g_src_sorted[i + 2]);
        int s3 = __ldg(&g_src_sorted[i + 3]);
        float4 v0 = __ldg((const float4*)(h + (size_t)s0 * D + lane * 4));
        float4 v1 = __ldg((const float4*)(h + (size_t)s1 * D + lane * 4));
        float4 v2 = __ldg((const float4*)(h + (size_t)s2 * D + lane * 4));
        float4 v3 = __ldg((const float4*)(h + (size_t)s3 * D + lane * 4));
        acc0.x += v0.x + v1.x;  acc1.x += v2.x + v3.x;
        acc0.y += v0.y + v1.y;  acc1.y += v2.y + v3.y;
        acc0.z += v0.z + v1.z;  acc1.z += v2.z + v3.z;
        acc0.w += v0.w + v1.w;  acc1.w += v2.w + v3.w;
    }
    for (; i < end; i++) {
        int s0 = __ldg(&g_src_sorted[i]);
        float4 v0 = __ldg((const float4*)(h + (size_t)s0 * D + lane * 4));
        acc0.x += v0.x; acc0.y += v0.y; acc0.z += v0.z; acc0.w += v0.w;
    }
    float inv = 1.0f / fmaxf((float)(end - beg), 1.0f);
    float4 r;
    r.x = (acc0.x + acc1.x) * inv;
    r.y = (acc0.y + acc1.y) * inv;
    r.z = (acc0.z + acc1.z) * inv;
    r.w = (acc0.w + acc1.w) * inv;
    *(float4*)(out + (size_t)gw * D + lane * 4) = r;
}

// -------- fused GEMM: out = A0 @ Wl^T + A1 @ Wr^T + b, optional ReLU --------
// block tile 64x128, 256 threads, 8x4 acc/thread. smem 96 KB.
template <bool RELU>
__global__ void __launch_bounds__(256, 2)
gemm_kernel(const float* __restrict__ A0, const float* __restrict__ A1,
            const float* __restrict__ Wl, const float* __restrict__ Wr,
            const float* __restrict__ bias, float* __restrict__ out) {
    extern __shared__ float smem[];
    float* As = smem;             // 64*128
    float* Ws = smem + 64 * D;    // 128*128 transposed: Ws[k][j]

    const int tid = threadIdx.x;
    const int trow = tid >> 5;
    const int tcol = tid & 31;
    const int row0 = blockIdx.x * 64;

    float acc[8][4];
#pragma unroll
    for (int i = 0; i < 8; i++)
#pragma unroll
        for (int j = 0; j < 4; j++) acc[i][j] = 0.f;

#pragma unroll
    for (int phase = 0; phase < 2; phase++) {
        const float* A = phase ? A1 : A0;
        const float* W = phase ? Wr : Wl;
        __syncthreads();
#pragma unroll
        for (int it = 0; it < 8; it++) {
            int idx = tid + it * 256;
            int kq = idx & 31;
            int r = idx >> 5;
            int row = row0 + r;
            float4 v = make_float4(0.f, 0.f, 0.f, 0.f);
            if (row < N_NODES) v = *(const float4*)(A + (size_t)row * D + kq * 4);
            *(float4*)(As + r * D + kq * 4) = v;
        }
#pragma unroll
        for (int it = 0; it < 16; it++) {
            int idx = tid + it * 256;
            int j = idx & 127;
            int kq = idx >> 7;
            float4 v = *(const float4*)(W + (size_t)j * D + kq * 4);
            Ws[(kq * 4 + 0) * D + j] = v.x;
            Ws[(kq * 4 + 1) * D + j] = v.y;
            Ws[(kq * 4 + 2) * D + j] = v.z;
            Ws[(kq * 4 + 3) * D + j] = v.w;
        }
        __syncthreads();

#pragma unroll 4
        for (int k4 = 0; k4 < 32; k4++) {
            float4 w0 = *(const float4*)(Ws + (k4 * 4 + 0) * D + tcol * 4);
            float4 w1 = *(const float4*)(Ws + (k4 * 4 + 1) * D + tcol * 4);
            float4 w2 = *(const float4*)(Ws + (k4 * 4 + 2) * D + tcol * 4);
            float4 w3 = *(const float4*)(Ws + (k4 * 4 + 3) * D + tcol * 4);
#pragma unroll
            for (int i = 0; i < 8; i++) {
                float4 a = *(const float4*)(As + (trow * 8 + i) * D + k4 * 4);
                acc[i][0] = fmaf(a.x, w0.x, acc[i][0]);
                acc[i][1] = fmaf(a.x, w0.y, acc[i][1]);
                acc[i][2] = fmaf(a.x, w0.z, acc[i][2]);
                acc[i][3] = fmaf(a.x, w0.w, acc[i][3]);
                acc[i][0] = fmaf(a.y, w1.x, acc[i][0]);
                acc[i][1] = fmaf(a.y, w1.y, acc[i][1]);
                acc[i][2] = fmaf(a.y, w1.z, acc[i][2]);
                acc[i][3] = fmaf(a.y, w1.w, acc[i][3]);
                acc[i][0] = fmaf(a.z, w2.x, acc[i][0]);
                acc[i][1] = fmaf(a.z, w2.y, acc[i][1]);
                acc[i][2] = fmaf(a.z, w2.z, acc[i][2]);
                acc[i][3] = fmaf(a.z, w2.w, acc[i][3]);
                acc[i][0] = fmaf(a.w, w3.x, acc[i][0]);
                acc[i][1] = fmaf(a.w, w3.y, acc[i][1]);
                acc[i][2] = fmaf(a.w, w3.z, acc[i][2]);
                acc[i][3] = fmaf(a.w, w3.w, acc[i][3]);
            }
        }
    }

    float4 b4 = *(const float4*)(bias + tcol * 4);
#pragma unroll
    for (int i = 0; i < 8; i++) {
        int row = row0 + trow * 8 + i;
        if (row < N_NODES) {
            float4 v;
            v.x = acc[i][0] + b4.x;
            v.y = acc[i][1] + b4.y;
            v.z = acc[i][2] + b4.z;
            v.w = acc[i][3] + b4.w;
            if (RELU) {
                v.x = fmaxf(v.x, 0.f); v.y = fmaxf(v.y, 0.f);
                v.z = fmaxf(v.z, 0.f); v.w = fmaxf(v.w, 0.f);
            }
            *(float4*)(out + (size_t)row * D + tcol * 4) = v;
        }
    }
}

// -------- batchnorm (non-atomic partials, idempotent) --------
__global__ void bn_stats(const float* __restrict__ h) {
    int col = threadIdx.x;                 // 128
    int r0 = blockIdx.x * BN_ROWS;         // 250 blocks x 200 rows
    float s = 0.f, s2 = 0.f;
#pragma unroll 4
    for (int r = r0; r < r0 + BN_ROWS; r++) {
        float v = h[(size_t)r * D + col];
        s += v;
        s2 += v * v;
    }
    g_part_s[blockIdx.x * D + col] = s;
    g_part_s2[blockIdx.x * D + col] = s2;
}

__global__ void bn_finalize(const float* __restrict__ gamma,
                            const float* __restrict__ beta) {
    int c = threadIdx.x;  // 128
    double s = 0.0, s2 = 0.0;
    for (int b = 0; b < BN_BLOCKS; b++) {
        s += (double)g_part_s[b * D + c];
        s2 += (double)g_part_s2[b * D + c];
    }
    double mu = s / (double)N_NODES;
    double var = s2 / (double)N_NODES - mu * mu;
    float inv = rsqrtf((float)var + 1e-5f);
    float sc = inv * gamma[c];
    g_bn_scale[c] = sc;
    g_bn_shift[c] = beta[c] - (float)mu * sc;
}

__global__ void bn_apply(float* __restrict__ h) {
    int i = blockIdx.x * blockDim.x + threadIdx.x;
    if (i < N_NODES * D) {
        int col = i & (D - 1);
        float v = fmaf(h[i], g_bn_scale[col], g_bn_shift[col]);
        h[i] = fmaxf(v, 0.f);
    }
}

// -------- launch --------
extern "C" void kernel_launch(void* const* d_in, const int* in_sizes, int n_in,
                              void* d_out, int out_size) {
    const float* x     = (const float*)d_in[0];
    const int*   ei    = (const int*)d_in[1];
    const float* Wl0   = (const float*)d_in[2];
    const float* bl0   = (const float*)d_in[3];
    const float* Wr0   = (const float*)d_in[4];
    const float* Wl1   = (const float*)d_in[5];
    const float* bl1   = (const float*)d_in[6];
    const float* Wr1   = (const float*)d_in[7];
    const float* Wl2   = (const float*)d_in[8];
    const float* bl2   = (const float*)d_in[9];
    const float* Wr2   = (const float*)d_in[10];
    const float* gamma = (const float*)d_in[11];
    const float* beta  = (const float*)d_in[12];
    float* out = (float*)d_out;

    const int* srcp = ei;
    const int* dstp = ei + N_EDGES;

    const int SMEM = (64 * D + D * D) * sizeof(float);  // 96 KB
    cudaFuncSetAttribute(gemm_kernel<true>,
                         cudaFuncAttributeMaxDynamicSharedMemorySize, SMEM);
    cudaFuncSetAttribute(gemm_kernel<false>,
                         cudaFuncAttributeMaxDynamicSharedMemorySize, SMEM);

    const int EB = (N_EDGES + 255) / 256;         // 3125
    const int AGGB = (N_NODES * 32 + 255) / 256;  // 6250
    const int GB = (N_NODES + 63) / 64;           // 782

    // CSR build — exactly 3 launches before the profiled slot
    hist_kernel<<<EB, 256>>>(dstp);               // #1
    scan_kernel<<<1, 1024>>>();                   // #2 (also resets g_cnt)
    scatter_kernel<<<EB, 256>>>(srcp, dstp);      // #3

    // layer 0
    agg_kernel<<<AGGB, 256>>>(x, g_mean);         // #4  <-- PROFILED SLOT
    gemm_kernel<true><<<GB, 256, SMEM>>>(g_mean, x, Wl0, Wr0, bl0, g_h0);

    // layer 1
    agg_kernel<<<AGGB, 256>>>(g_h0, g_mean);
    gemm_kernel<false><<<GB, 256, SMEM>>>(g_mean, g_h0, Wl1, Wr1, bl1, g_h1);

    // relu(batchnorm(h1))
    bn_stats<<<BN_BLOCKS, 128>>>(g_h1);
    bn_finalize<<<1, 128>>>(gamma, beta);
    bn_apply<<<(N_NODES * D + 255) / 256, 256>>>(g_h1);

    // layer 2
    agg_kernel<<<AGGB, 256>>>(g_h1, g_mean);
    gemm_kernel<false><<<GB, 256, SMEM>>>(g_mean, g_h1, Wl2, Wr2, bl2, out);
}

// round 5
// speedup vs baseline: 10.1189x; 10.1189x over previous
#include <cuda_runtime.h>
#include <cuda_bf16.h>

#define NN 50000
#define NE 800000
#define D 128
#define NB 148
#define NT 512
#define GS (NB * NT)
#define NWARPS (NT / 32)
#define CHUNK ((NN + NB - 1) / NB)   // 338 nodes per block

// -------- device scratch (no runtime allocation allowed) --------
__device__ unsigned g_gen = 0;
__device__ unsigned g_arrive = 0;
__device__ int   g_cnt[NN];          // zero on entry (zero-init / reset each pass)
__device__ int   g_off[NN + 1];
__device__ int   g_pos[NN];
__device__ int   g_srcs[NE];
__device__ int   g_bsum[NB];
__device__ int   g_boff[NB];
__device__ float g_mean[NN * D];
__device__ float g_h0[NN * D];
__device__ float g_h1[NN * D];
__device__ float g_ps[NB * D];
__device__ float g_ps2[NB * D];
__device__ float g_scale[D];
__device__ float g_shift[D];

// -------- grid-wide software barrier (all NB blocks co-resident) --------
__device__ __forceinline__ void gbar() {
    __syncthreads();
    if (threadIdx.x == 0) {
        __threadfence();
        unsigned gen = atomicAdd(&g_gen, 0u);
        unsigned arrived = atomicAdd(&g_arrive, 1u) + 1u;
        if (arrived == NB) {
            atomicExch(&g_arrive, 0u);
            __threadfence();
            atomicAdd(&g_gen, 1u);
        } else {
            while (atomicAdd(&g_gen, 0u) == gen) { __nanosleep(128); }
        }
        __threadfence();
    }
    __syncthreads();
}

// -------- mean aggregation: one warp per node --------
__device__ __forceinline__ void agg_phase(const float* __restrict__ h,
                                          float* __restrict__ o) {
    const int lane = threadIdx.x & 31;
    const int warp = threadIdx.x >> 5;
    const int gw0 = blockIdx.x * NWARPS + warp;
    for (int n = gw0; n < NN; n += NB * NWARPS) {
        int beg = g_off[n];
        int end = g_off[n + 1];
        float4 a0 = make_float4(0.f, 0.f, 0.f, 0.f);
        float4 a1 = make_float4(0.f, 0.f, 0.f, 0.f);
        int i = beg;
        for (; i + 3 < end; i += 4) {
            int s0 = __ldg(&g_srcs[i]);
            int s1 = __ldg(&g_srcs[i + 1]);
            int s2 = __ldg(&g_srcs[i + 2]);
            int s3 = __ldg(&g_srcs[i + 3]);
            float4 v0 = __ldg((const float4*)(h + s0 * D + lane * 4));
            float4 v1 = __ldg((const float4*)(h + s1 * D + lane * 4));
            float4 v2 = __ldg((const float4*)(h + s2 * D + lane * 4));
            float4 v3 = __ldg((const float4*)(h + s3 * D + lane * 4));
            a0.x += v0.x + v1.x;  a1.x += v2.x + v3.x;
            a0.y += v0.y + v1.y;  a1.y += v2.y + v3.y;
            a0.z += v0.z + v1.z;  a1.z += v2.z + v3.z;
            a0.w += v0.w + v1.w;  a1.w += v2.w + v3.w;
        }
        for (; i < end; i++) {
            int s0 = __ldg(&g_srcs[i]);
            float4 v0 = __ldg((const float4*)(h + s0 * D + lane * 4));
            a0.x += v0.x; a0.y += v0.y; a0.z += v0.z; a0.w += v0.w;
        }
        float inv = 1.0f / fmaxf((float)(end - beg), 1.0f);
        float4 r;
        r.x = (a0.x + a1.x) * inv;
        r.y = (a0.y + a1.y) * inv;
        r.z = (a0.z + a1.z) * inv;
        r.w = (a0.w + a1.w) * inv;
        *(float4*)(o + n * D + lane * 4) = r;
    }
}

// -------- fused dual GEMM: out = A0@Wl^T + A1@Wr^T + b [relu] --------
// tile 64 rows x 128 cols, 512 threads: warp = 4 rows, lane = 4 cols.
__device__ __forceinline__ void gemm_phase(const float* __restrict__ A0,
                                           const float* __restrict__ A1,
                                           const float* __restrict__ Wl,
                                           const float* __restrict__ Wr,
                                           const float* __restrict__ bias,
                                           float* __restrict__ out,
                                           bool relu, float* sm) {
    float* As = sm;            // 64*128 floats
    float* Ws = sm + 64 * D;   // 128*128 floats, transposed: Ws[k][j]
    const int tid = threadIdx.x;
    const int warp = tid >> 5;
    const int lane = tid & 31;
    const int NTILES = (NN + 63) / 64;   // 782

    for (int t = blockIdx.x; t < NTILES; t += NB) {
        const int row0 = t * 64;
        float acc[4][4];
#pragma unroll
        for (int i = 0; i < 4; i++)
#pragma unroll
            for (int j = 0; j < 4; j++) acc[i][j] = 0.f;

#pragma unroll
        for (int ph = 0; ph < 2; ph++) {
            const float* A = ph ? A1 : A0;
            const float* W = ph ? Wr : Wl;
            __syncthreads();
#pragma unroll
            for (int it = 0; it < 4; it++) {
                int idx = tid + it * NT;      // 0..2047 float4 slots
                int kq = idx & 31;
                int r = idx >> 5;
                int row = row0 + r;
                float4 v = make_float4(0.f, 0.f, 0.f, 0.f);
                if (row < NN) v = *(const float4*)(A + row * D + kq * 4);
                *(float4*)(As + r * D + kq * 4) = v;
            }
#pragma unroll
            for (int it = 0; it < 8; it++) {
                int idx = tid + it * NT;      // 0..4095
                int j = idx & 127;
                int kq = idx >> 7;
                float4 v = *(const float4*)(W + j * D + kq * 4);
                Ws[(kq * 4 + 0) * D + j] = v.x;
                Ws[(kq * 4 + 1) * D + j] = v.y;
                Ws[(kq * 4 + 2) * D + j] = v.z;
                Ws[(kq * 4 + 3) * D + j] = v.w;
            }
            __syncthreads();

#pragma unroll 2
            for (int k4 = 0; k4 < 32; k4++) {
                float4 w0 = *(const float4*)(Ws + (k4 * 4 + 0) * D + lane * 4);
                float4 w1 = *(const float4*)(Ws + (k4 * 4 + 1) * D + lane * 4);
                float4 w2 = *(const float4*)(Ws + (k4 * 4 + 2) * D + lane * 4);
                float4 w3 = *(const float4*)(Ws + (k4 * 4 + 3) * D + lane * 4);
#pragma unroll
                for (int i = 0; i < 4; i++) {
                    float4 a = *(const float4*)(As + (warp * 4 + i) * D + k4 * 4);
                    acc[i][0] = fmaf(a.x, w0.x, acc[i][0]);
                    acc[i][1] = fmaf(a.x, w0.y, acc[i][1]);
                    acc[i][2] = fmaf(a.x, w0.z, acc[i][2]);
                    acc[i][3] = fmaf(a.x, w0.w, acc[i][3]);
                    acc[i][0] = fmaf(a.y, w1.x, acc[i][0]);
                    acc[i][1] = fmaf(a.y, w1.y, acc[i][1]);
                    acc[i][2] = fmaf(a.y, w1.z, acc[i][2]);
                    acc[i][3] = fmaf(a.y, w1.w, acc[i][3]);
                    acc[i][0] = fmaf(a.z, w2.x, acc[i][0]);
                    acc[i][1] = fmaf(a.z, w2.y, acc[i][1]);
                    acc[i][2] = fmaf(a.z, w2.z, acc[i][2]);
                    acc[i][3] = fmaf(a.z, w2.w, acc[i][3]);
                    acc[i][0] = fmaf(a.w, w3.x, acc[i][0]);
                    acc[i][1] = fmaf(a.w, w3.y, acc[i][1]);
                    acc[i][2] = fmaf(a.w, w3.z, acc[i][2]);
                    acc[i][3] = fmaf(a.w, w3.w, acc[i][3]);
                }
            }
        }

        float4 b4 = *(const float4*)(bias + lane * 4);
#pragma unroll
        for (int i = 0; i < 4; i++) {
            int row = row0 + warp * 4 + i;
            if (row < NN) {
                float4 v;
                v.x = acc[i][0] + b4.x;
                v.y = acc[i][1] + b4.y;
                v.z = acc[i][2] + b4.z;
                v.w = acc[i][3] + b4.w;
                if (relu) {
                    v.x = fmaxf(v.x, 0.f); v.y = fmaxf(v.y, 0.f);
                    v.z = fmaxf(v.z, 0.f); v.w = fmaxf(v.w, 0.f);
                }
                *(float4*)(out + row * D + lane * 4) = v;
            }
        }
    }
}

// -------- the mono-kernel --------
__global__ void __launch_bounds__(NT, 1)
mono_kernel(const float* __restrict__ x,
            const int* __restrict__ src, const int* __restrict__ dst,
            const float* __restrict__ Wl0, const float* __restrict__ bl0,
            const float* __restrict__ Wr0,
            const float* __restrict__ Wl1, const float* __restrict__ bl1,
            const float* __restrict__ Wr1,
            const float* __restrict__ Wl2, const float* __restrict__ bl2,
            const float* __restrict__ Wr2,
            const float* __restrict__ gamma, const float* __restrict__ beta,
            float* __restrict__ out) {
    extern __shared__ float sm[];
    const int tid = threadIdx.x;
    const int bid = blockIdx.x;
    const int gt = bid * NT + tid;
    const int lane = tid & 31;
    const int warp = tid >> 5;

    // ---- phase 1: histogram of dst ----
    for (int e = gt; e < NE; e += GS) atomicAdd(&g_cnt[dst[e]], 1);
    gbar();

    // ---- phase 2: per-block chunk sums ----
    {
        __shared__ int red[NWARPS];
        int base = bid * CHUNK;
        int v = 0;
        for (int i = tid; i < CHUNK; i += NT) {
            int idx = base + i;
            if (idx < NN) v += g_cnt[idx];
        }
#pragma unroll
        for (int o = 16; o > 0; o >>= 1) v += __shfl_down_sync(0xffffffffu, v, o);
        if (lane == 0) red[warp] = v;
        __syncthreads();
        if (warp == 0) {
            int w = (lane < NWARPS) ? red[lane] : 0;
#pragma unroll
            for (int o = 8; o > 0; o >>= 1) w += __shfl_down_sync(0xffffffffu, w, o);
            if (lane == 0) g_bsum[bid] = w;
        }
    }
    gbar();

    // ---- phase 3: block 0 scans block sums ----
    if (bid == 0 && tid == 0) {
        int run = 0;
        for (int b = 0; b < NB; b++) { g_boff[b] = run; run += g_bsum[b]; }
        g_off[NN] = run;
    }
    gbar();

    // ---- phase 4: write offsets (block scan of chunk), reset g_cnt ----
    {
        __shared__ int wsum[NWARPS];
        int base = bid * CHUNK;
        int idx = base + tid;
        int v = (tid < CHUNK && idx < NN) ? g_cnt[idx] : 0;
        int inc = v;
#pragma unroll
        for (int o = 1; o < 32; o <<= 1) {
            int u = __shfl_up_sync(0xffffffffu, inc, o);
            if (lane >= o) inc += u;
        }
        if (lane == 31) wsum[warp] = inc;
        __syncthreads();
        if (warp == 0) {
            int w = (lane < NWARPS) ? wsum[lane] : 0;
            int wi = w;
#pragma unroll
            for (int o = 1; o < NWARPS; o <<= 1) {
                int u = __shfl_up_sync(0xffffffffu, wi, o);
                if (lane >= o) wi += u;
            }
            if (lane < NWARPS) wsum[lane] = wi - w;
        }
        __syncthreads();
        int excl = g_boff[bid] + wsum[warp] + inc - v;
        if (tid < CHUNK && idx < NN) {
            g_off[idx] = excl;
            g_pos[idx] = excl;
            g_cnt[idx] = 0;   // reset for next graph replay
        }
    }
    gbar();

    // ---- phase 5: scatter src by dst ----
    for (int e = gt; e < NE; e += GS) {
        int p = atomicAdd(&g_pos[dst[e]], 1);
        g_srcs[p] = src[e];
    }
    gbar();

    // ---- layer 0 ----
    agg_phase(x, g_mean);
    gbar();
    gemm_phase(g_mean, x, Wl0, Wr0, bl0, g_h0, true, sm);
    gbar();

    // ---- layer 1 ----
    agg_phase(g_h0, g_mean);
    gbar();
    gemm_phase(g_mean, g_h0, Wl1, Wr1, bl1, g_h1, false, sm);
    gbar();

    // ---- batchnorm stats (per-block partials) ----
    {
        float* smf = sm;  // reuse: [4][128] x 2
        int col = tid & 127;
        int rg = tid >> 7;  // 0..3
        int base = bid * CHUNK;
        int lim = min(base + CHUNK, NN);
        float s = 0.f, s2 = 0.f;
        for (int r = base + rg; r < lim; r += 4) {
            float v = g_h1[r * D + col];
            s += v;
            s2 += v * v;
        }
        __syncthreads();
        smf[rg * 128 + col] = s;
        smf[512 + rg * 128 + col] = s2;
        __syncthreads();
        if (rg == 0) {
            float ts = smf[col] + smf[128 + col] + smf[256 + col] + smf[384 + col];
            float t2 = smf[512 + col] + smf[640 + col] + smf[768 + col] + smf[896 + col];
            g_ps[bid * D + col] = ts;
            g_ps2[bid * D + col] = t2;
        }
    }
    gbar();

    // ---- batchnorm finalize (block 0) ----
    if (bid == 0 && tid < D) {
        double s = 0.0, s2 = 0.0;
        for (int b = 0; b < NB; b++) {
            s += (double)g_ps[b * D + tid];
            s2 += (double)g_ps2[b * D + tid];
        }
        double mu = s / (double)NN;
        double var = s2 / (double)NN - mu * mu;
        float inv = rsqrtf((float)var + 1e-5f);
        float sc = inv * gamma[tid];
        g_scale[tid] = sc;
        g_shift[tid] = beta[tid] - (float)mu * sc;
    }
    gbar();

    // ---- batchnorm apply + relu ----
    for (int i = gt; i < NN * (D / 4); i += GS) {
        float4 v = ((float4*)g_h1)[i];
        int c = (i & 31) * 4;
        v.x = fmaxf(fmaf(v.x, g_scale[c + 0], g_shift[c + 0]), 0.f);
        v.y = fmaxf(fmaf(v.y, g_scale[c + 1], g_shift[c + 1]), 0.f);
        v.z = fmaxf(fmaf(v.z, g_scale[c + 2], g_shift[c + 2]), 0.f);
        v.w = fmaxf(fmaf(v.w, g_scale[c + 3], g_shift[c + 3]), 0.f);
        ((float4*)g_h1)[i] = v;
    }
    gbar();

    // ---- layer 2 ----
    agg_phase(g_h1, g_mean);
    gbar();
    gemm_phase(g_mean, g_h1, Wl2, Wr2, bl2, out, false, sm);
}

// -------- launch --------
extern "C" void kernel_launch(void* const* d_in, const int* in_sizes, int n_in,
                              void* d_out, int out_size) {
    const float* x     = (const float*)d_in[0];
    const int*   ei    = (const int*)d_in[1];
    const float* Wl0   = (const float*)d_in[2];
    const float* bl0   = (const float*)d_in[3];
    const float* Wr0   = (const float*)d_in[4];
    const float* Wl1   = (const float*)d_in[5];
    const float* bl1   = (const float*)d_in[6];
    const float* Wr1   = (const float*)d_in[7];
    const float* Wl2   = (const float*)d_in[8];
    const float* bl2   = (const float*)d_in[9];
    const float* Wr2   = (const float*)d_in[10];
    const float* gamma = (const float*)d_in[11];
    const float* beta  = (const float*)d_in[12];
    float* out = (float*)d_out;

    const int* srcp = ei;
    const int* dstp = ei + NE;

    const int SMEM = (64 * D + D * D) * sizeof(float);  // 96 KB
    static bool attr_set = false;
    if (!attr_set) {
        cudaFuncSetAttribute(mono_kernel,
                             cudaFuncAttributeMaxDynamicSharedMemorySize, SMEM);
        attr_set = true;
    }

    mono_kernel<<<NB, NT, SMEM>>>(x, srcp, dstp,
                                  Wl0, bl0, Wr0,
                                  Wl1, bl1, Wr1,
                                  Wl2, bl2, Wr2,
                                  gamma, beta, out);
}

// round 6
// speedup vs baseline: 12.6475x; 1.2499x over previous
#include <cuda_runtime.h>
#include <cuda_bf16.h>

#define NN 50000
#define NE 800000
#define D 128
#define NB 148
#define NT 512
#define GS (NB * NT)
#define NWARPS (NT / 32)
#define CHUNK ((NN + NB - 1) / NB)   // 338 nodes per block

typedef unsigned long long u64;

// -------- device scratch (no runtime allocation allowed) --------
__device__ unsigned g_gen = 0;
__device__ unsigned g_arrive = 0;
__device__ int   g_cnt[NN];          // zero-init; reset each pass
__device__ int   g_off[NN + 1];
__device__ int   g_pos[NN];
__device__ int   g_srcs[NE];
__device__ int   g_bsum[NB];
__device__ float g_mean[NN * D];
__device__ float g_h0[NN * D];
__device__ float g_h1[NN * D];
__device__ float g_ps[NB * D];
__device__ float g_ps2[NB * D];

// -------- grid-wide software barrier (all NB blocks co-resident) --------
__device__ __forceinline__ void gbar() {
    __syncthreads();
    if (threadIdx.x == 0) {
        __threadfence();
        unsigned gen = atomicAdd(&g_gen, 0u);
        unsigned arrived = atomicAdd(&g_arrive, 1u) + 1u;
        if (arrived == NB) {
            atomicExch(&g_arrive, 0u);
            __threadfence();
            atomicAdd(&g_gen, 1u);
        } else {
            while (atomicAdd(&g_gen, 0u) == gen) { __nanosleep(128); }
        }
        __threadfence();
    }
    __syncthreads();
}

// -------- mean aggregation: one warp per node --------
__device__ __forceinline__ void agg_phase(const float* __restrict__ h,
                                          float* __restrict__ o) {
    const int lane = threadIdx.x & 31;
    const int warp = threadIdx.x >> 5;
    const int gw0 = blockIdx.x * NWARPS + warp;
    for (int n = gw0; n < NN; n += NB * NWARPS) {
        int beg = g_off[n];
        int end = g_off[n + 1];
        float4 a0 = make_float4(0.f, 0.f, 0.f, 0.f);
        float4 a1 = make_float4(0.f, 0.f, 0.f, 0.f);
        int i = beg;
        for (; i + 7 < end; i += 8) {
            int s0 = __ldg(&g_srcs[i]);
            int s1 = __ldg(&g_srcs[i + 1]);
            int s2 = __ldg(&g_srcs[i + 2]);
            int s3 = __ldg(&g_srcs[i + 3]);
            int s4 = __ldg(&g_srcs[i + 4]);
            int s5 = __ldg(&g_srcs[i + 5]);
            int s6 = __ldg(&g_srcs[i + 6]);
            int s7 = __ldg(&g_srcs[i + 7]);
            float4 v0 = __ldg((const float4*)(h + s0 * D + lane * 4));
            float4 v1 = __ldg((const float4*)(h + s1 * D + lane * 4));
            float4 v2 = __ldg((const float4*)(h + s2 * D + lane * 4));
            float4 v3 = __ldg((const float4*)(h + s3 * D + lane * 4));
            float4 v4 = __ldg((const float4*)(h + s4 * D + lane * 4));
            float4 v5 = __ldg((const float4*)(h + s5 * D + lane * 4));
            float4 v6 = __ldg((const float4*)(h + s6 * D + lane * 4));
            float4 v7 = __ldg((const float4*)(h + s7 * D + lane * 4));
            a0.x += (v0.x + v1.x) + (v2.x + v3.x);
            a0.y += (v0.y + v1.y) + (v2.y + v3.y);
            a0.z += (v0.z + v1.z) + (v2.z + v3.z);
            a0.w += (v0.w + v1.w) + (v2.w + v3.w);
            a1.x += (v4.x + v5.x) + (v6.x + v7.x);
            a1.y += (v4.y + v5.y) + (v6.y + v7.y);
            a1.z += (v4.z + v5.z) + (v6.z + v7.z);
            a1.w += (v4.w + v5.w) + (v6.w + v7.w);
        }
        for (; i < end; i++) {
            int s0 = __ldg(&g_srcs[i]);
            float4 v0 = __ldg((const float4*)(h + s0 * D + lane * 4));
            a0.x += v0.x; a0.y += v0.y; a0.z += v0.z; a0.w += v0.w;
        }
        float inv = 1.0f / fmaxf((float)(end - beg), 1.0f);
        float4 r;
        r.x = (a0.x + a1.x) * inv;
        r.y = (a0.y + a1.y) * inv;
        r.z = (a0.z + a1.z) * inv;
        r.w = (a0.w + a1.w) * inv;
        *(float4*)(o + n * D + lane * 4) = r;
    }
}

// -------- f32x2 packed helpers --------
__device__ __forceinline__ u64 pack_dup(float v) {
    u64 r;
    asm("mov.b64 %0, {%1, %1};" : "=l"(r) : "f"(v));
    return r;
}
__device__ __forceinline__ void fma2(u64& acc, u64 a, u64 b) {
    asm("fma.rn.f32x2 %0, %1, %2, %0;" : "+l"(acc) : "l"(a), "l"(b));
}
__device__ __forceinline__ void unpack2(u64 v, float& lo, float& hi) {
    asm("mov.b64 {%0, %1}, %2;" : "=f"(lo), "=f"(hi) : "l"(v));
}

// -------- fused dual GEMM via FFMA2: out = A0@Wl^T + A1@Wr^T + b [relu] --------
// tile 128 rows x 128 cols, 512 threads: warp = 8 rows (4 row-pairs), lane = 4 cols.
// As_t: A transposed [k][row], XOR-swizzled rows (swz = (k>>2)*2 & 31).
// Ws:   W transposed [k][j].
__device__ __forceinline__ void gemm_phase(const float* __restrict__ A0,
                                           const float* __restrict__ A1,
                                           const float* __restrict__ Wl,
                                           const float* __restrict__ Wr,
                                           const float* __restrict__ bias,
                                           float* __restrict__ out,
                                           bool relu, float* sm) {
    float* As_t = sm;            // 128*128 floats = 64 KB
    float* Ws = sm + D * D;      // 128*128 floats = 64 KB
    const int tid = threadIdx.x;
    const int warp = tid >> 5;
    const int lane = tid & 31;
    const int rbase = warp * 8;
    const int NTILES = (NN + 127) / 128;   // 391

    for (int t = blockIdx.x; t < NTILES; t += NB) {
        const int row0 = t * 128;
        u64 acc[4][4];
#pragma unroll
        for (int i = 0; i < 4; i++)
#pragma unroll
            for (int c = 0; c < 4; c++) acc[i][c] = 0ull;

#pragma unroll
        for (int ph = 0; ph < 2; ph++) {
            const float* A = ph ? A1 : A0;
            const float* W = ph ? Wr : Wl;
            __syncthreads();
            // load A tile transposed + swizzled
#pragma unroll
            for (int it = 0; it < 8; it++) {
                int idx = tid + it * NT;      // 0..4095 float4 slots
                int kq = idx & 31;
                int r = idx >> 5;
                int row = row0 + r;
                float4 v = make_float4(0.f, 0.f, 0.f, 0.f);
                if (row < NN) v = *(const float4*)(A + row * D + kq * 4);
                int rs = r ^ ((kq << 1) & 31);
                As_t[(kq * 4 + 0) * D + rs] = v.x;
                As_t[(kq * 4 + 1) * D + rs] = v.y;
                As_t[(kq * 4 + 2) * D + rs] = v.z;
                As_t[(kq * 4 + 3) * D + rs] = v.w;
            }
            // load W transposed: Ws[k][j] = W[j][k]
#pragma unroll
            for (int it = 0; it < 8; it++) {
                int idx = tid + it * NT;
                int j = idx & 127;
                int kq = idx >> 7;
                float4 v = *(const float4*)(W + j * D + kq * 4);
                Ws[(kq * 4 + 0) * D + j] = v.x;
                Ws[(kq * 4 + 1) * D + j] = v.y;
                Ws[(kq * 4 + 2) * D + j] = v.z;
                Ws[(kq * 4 + 3) * D + j] = v.w;
            }
            __syncthreads();

#pragma unroll 2
            for (int kq = 0; kq < 32; kq++) {
                const int swz = (kq << 1) & 31;
                // row-pair offsets within swizzled row (even ^ even stays even)
                const int r0s = (rbase + 0) ^ swz;
                const int r1s = (rbase + 2) ^ swz;
                const int r2s = (rbase + 4) ^ swz;
                const int r3s = (rbase + 6) ^ swz;
#pragma unroll
                for (int j = 0; j < 4; j++) {
                    const int k = kq * 4 + j;
                    const float* atk = As_t + k * D;
                    u64 a0 = *(const u64*)(atk + r0s);
                    u64 a1 = *(const u64*)(atk + r1s);
                    u64 a2 = *(const u64*)(atk + r2s);
                    u64 a3 = *(const u64*)(atk + r3s);
                    float4 wv = *(const float4*)(Ws + k * D + lane * 4);
                    u64 w0 = pack_dup(wv.x);
                    u64 w1 = pack_dup(wv.y);
                    u64 w2 = pack_dup(wv.z);
                    u64 w3 = pack_dup(wv.w);
                    fma2(acc[0][0], a0, w0); fma2(acc[0][1], a0, w1);
                    fma2(acc[0][2], a0, w2); fma2(acc[0][3], a0, w3);
                    fma2(acc[1][0], a1, w0); fma2(acc[1][1], a1, w1);
                    fma2(acc[1][2], a1, w2); fma2(acc[1][3], a1, w3);
                    fma2(acc[2][0], a2, w0); fma2(acc[2][1], a2, w1);
                    fma2(acc[2][2], a2, w2); fma2(acc[2][3], a2, w3);
                    fma2(acc[3][0], a3, w0); fma2(acc[3][1], a3, w1);
                    fma2(acc[3][2], a3, w2); fma2(acc[3][3], a3, w3);
                }
            }
        }

        // epilogue: unpack row-pairs, add bias, optional relu, store
        float4 b4 = *(const float4*)(bias + lane * 4);
#pragma unroll
        for (int i = 0; i < 4; i++) {
            float lo0, hi0, lo1, hi1, lo2, hi2, lo3, hi3;
            unpack2(acc[i][0], lo0, hi0);
            unpack2(acc[i][1], lo1, hi1);
            unpack2(acc[i][2], lo2, hi2);
            unpack2(acc[i][3], lo3, hi3);
            int row_lo = row0 + rbase + 2 * i;
            if (row_lo < NN) {
                float4 v;
                v.x = lo0 + b4.x; v.y = lo1 + b4.y;
                v.z = lo2 + b4.z; v.w = lo3 + b4.w;
                if (relu) {
                    v.x = fmaxf(v.x, 0.f); v.y = fmaxf(v.y, 0.f);
                    v.z = fmaxf(v.z, 0.f); v.w = fmaxf(v.w, 0.f);
                }
                *(float4*)(out + row_lo * D + lane * 4) = v;
            }
            if (row_lo + 1 < NN) {
                float4 v;
                v.x = hi0 + b4.x; v.y = hi1 + b4.y;
                v.z = hi2 + b4.z; v.w = hi3 + b4.w;
                if (relu) {
                    v.x = fmaxf(v.x, 0.f); v.y = fmaxf(v.y, 0.f);
                    v.z = fmaxf(v.z, 0.f); v.w = fmaxf(v.w, 0.f);
                }
                *(float4*)(out + (row_lo + 1) * D + lane * 4) = v;
            }
        }
    }
}

// -------- the mono-kernel --------
__global__ void __launch_bounds__(NT, 1)
mono_kernel(const float* __restrict__ x,
            const int* __restrict__ src, const int* __restrict__ dst,
            const float* __restrict__ Wl0, const float* __restrict__ bl0,
            const float* __restrict__ Wr0,
            const float* __restrict__ Wl1, const float* __restrict__ bl1,
            const float* __restrict__ Wr1,
            const float* __restrict__ Wl2, const float* __restrict__ bl2,
            const float* __restrict__ Wr2,
            const float* __restrict__ gamma, const float* __restrict__ beta,
            float* __restrict__ out) {
    extern __shared__ float sm[];
    const int tid = threadIdx.x;
    const int bid = blockIdx.x;
    const int gt = bid * NT + tid;
    const int lane = tid & 31;
    const int warp = tid >> 5;

    // ---- phase 1: histogram of dst ----
    for (int e = gt; e < NE; e += GS) atomicAdd(&g_cnt[dst[e]], 1);
    gbar();

    // ---- phase 2: per-block chunk sums ----
    {
        __shared__ int red[NWARPS];
        int base = bid * CHUNK;
        int v = 0;
        for (int i = tid; i < CHUNK; i += NT) {
            int idx = base + i;
            if (idx < NN) v += g_cnt[idx];
        }
#pragma unroll
        for (int o = 16; o > 0; o >>= 1) v += __shfl_down_sync(0xffffffffu, v, o);
        if (lane == 0) red[warp] = v;
        __syncthreads();
        if (warp == 0) {
            int w = (lane < NWARPS) ? red[lane] : 0;
#pragma unroll
            for (int o = 8; o > 0; o >>= 1) w += __shfl_down_sync(0xffffffffu, w, o);
            if (lane == 0) g_bsum[bid] = w;
        }
    }
    gbar();

    // ---- phase 3: every block scans block sums locally (smem serial; ~0.3us) ----
    __shared__ int s_boff;
    {
        __shared__ int sb[NB];
        if (tid < NB) sb[tid] = g_bsum[tid];
        __syncthreads();
        if (tid == 0) {
            int run = 0;
            for (int b = 0; b < NB; b++) { int v = sb[b]; sb[b] = run; run += v; }
            s_boff = sb[bid];
        }
        __syncthreads();
        if (bid == NB - 1 && tid == 0) g_off[NN] = NE;
    }

    // ---- phase 4: write offsets (block scan of chunk), reset g_cnt ----
    {
        __shared__ int wsum[NWARPS];
        int base = bid * CHUNK;
        int idx = base + tid;
        int v = (tid < CHUNK && idx < NN) ? g_cnt[idx] : 0;
        int inc = v;
#pragma unroll
        for (int o = 1; o < 32; o <<= 1) {
            int u = __shfl_up_sync(0xffffffffu, inc, o);
            if (lane >= o) inc += u;
        }
        if (lane == 31) wsum[warp] = inc;
        __syncthreads();
        if (warp == 0) {
            int w = (lane < NWARPS) ? wsum[lane] : 0;
            int wi = w;
#pragma unroll
            for (int o = 1; o < NWARPS; o <<= 1) {
                int u = __shfl_up_sync(0xffffffffu, wi, o);
                if (lane >= o) wi += u;
            }
            if (lane < NWARPS) wsum[lane] = wi - w;
        }
        __syncthreads();
        int excl = s_boff + wsum[warp] + inc - v;
        if (tid < CHUNK && idx < NN) {
            g_off[idx] = excl;
            g_pos[idx] = excl;
            g_cnt[idx] = 0;   // reset for next graph replay
        }
    }
    gbar();

    // ---- phase 5: scatter src by dst ----
    for (int e = gt; e < NE; e += GS) {
        int p = atomicAdd(&g_pos[dst[e]], 1);
        g_srcs[p] = src[e];
    }
    gbar();

    // ---- layer 0 ----
    agg_phase(x, g_mean);
    gbar();
    gemm_phase(g_mean, x, Wl0, Wr0, bl0, g_h0, true, sm);
    gbar();

    // ---- layer 1 ----
    agg_phase(g_h0, g_mean);
    gbar();
    gemm_phase(g_mean, g_h0, Wl1, Wr1, bl1, g_h1, false, sm);
    gbar();

    // ---- batchnorm stats (per-block partials) ----
    {
        float* smf = sm;  // reuse gemm smem
        int col = tid & 127;
        int rg = tid >> 7;  // 0..3
        int base = bid * CHUNK;
        int lim = min(base + CHUNK, NN);
        float s = 0.f, s2 = 0.f;
        for (int r = base + rg; r < lim; r += 4) {
            float v = g_h1[r * D + col];
            s += v;
            s2 += v * v;
        }
        __syncthreads();
        smf[rg * 128 + col] = s;
        smf[512 + rg * 128 + col] = s2;
        __syncthreads();
        if (rg == 0) {
            float ts = smf[col] + smf[128 + col] + smf[256 + col] + smf[384 + col];
            float t2 = smf[512 + col] + smf[640 + col] + smf[768 + col] + smf[896 + col];
            g_ps[bid * D + col] = ts;
            g_ps2[bid * D + col] = t2;
        }
    }
    gbar();

    // ---- batchnorm finalize (replicated per block) + apply + relu ----
    {
        __shared__ float s_scale[D], s_shift[D];
        __shared__ float r1[NT], r2[NT];
        int col = tid & 127;
        int part = tid >> 7;  // 0..3
        float s = 0.f, s2 = 0.f;
        for (int b = part; b < NB; b += 4) {
            s += g_ps[b * D + col];
            s2 += g_ps2[b * D + col];
        }
        r1[tid] = s; r2[tid] = s2;
        __syncthreads();
        if (part == 0) {
            double S = (double)r1[col] + (double)r1[col + 128] +
                       (double)r1[col + 256] + (double)r1[col + 384];
            double S2 = (double)r2[col] + (double)r2[col + 128] +
                        (double)r2[col + 256] + (double)r2[col + 384];
            double mu = S / (double)NN;
            double var = S2 / (double)NN - mu * mu;
            float inv = rsqrtf((float)var + 1e-5f);
            float sc = inv * gamma[col];
            s_scale[col] = sc;
            s_shift[col] = beta[col] - (float)mu * sc;
        }
        __syncthreads();
        for (int i = gt; i < NN * (D / 4); i += GS) {
            float4 v = ((float4*)g_h1)[i];
            int c = (i & 31) * 4;
            v.x = fmaxf(fmaf(v.x, s_scale[c + 0], s_shift[c + 0]), 0.f);
            v.y = fmaxf(fmaf(v.y, s_scale[c + 1], s_shift[c + 1]), 0.f);
            v.z = fmaxf(fmaf(v.z, s_scale[c + 2], s_shift[c + 2]), 0.f);
            v.w = fmaxf(fmaf(v.w, s_scale[c + 3], s_shift[c + 3]), 0.f);
            ((float4*)g_h1)[i] = v;
        }
    }
    gbar();

    // ---- layer 2 ----
    agg_phase(g_h1, g_mean);
    gbar();
    gemm_phase(g_mean, g_h1, Wl2, Wr2, bl2, out, false, sm);
}

// -------- launch --------
extern "C" void kernel_launch(void* const* d_in, const int* in_sizes, int n_in,
                              void* d_out, int out_size) {
    const float* x     = (const float*)d_in[0];
    const int*   ei    = (const int*)d_in[1];
    const float* Wl0   = (const float*)d_in[2];
    const float* bl0   = (const float*)d_in[3];
    const float* Wr0   = (const float*)d_in[4];
    const float* Wl1   = (const float*)d_in[5];
    const float* bl1   = (const float*)d_in[6];
    const float* Wr1   = (const float*)d_in[7];
    const float* Wl2   = (const float*)d_in[8];
    const float* bl2   = (const float*)d_in[9];
    const float* Wr2   = (const float*)d_in[10];
    const float* gamma = (const float*)d_in[11];
    const float* beta  = (const float*)d_in[12];
    float* out = (float*)d_out;

    const int* srcp = ei;
    const int* dstp = ei + NE;

    const int SMEM = 2 * D * D * sizeof(float);  // 128 KB dynamic
    static bool attr_set = false;
    if (!attr_set) {
        cudaFuncSetAttribute(mono_kernel,
                             cudaFuncAttributeMaxDynamicSharedMemorySize, SMEM);
        attr_set = true;
    }

    mono_kernel<<<NB, NT, SMEM>>>(x, srcp, dstp,
                                  Wl0, bl0, Wr0,
                                  Wl1, bl1, Wr1,
                                  Wl2, bl2, Wr2,
                                  gamma, beta, out);
}

// round 8
// speedup vs baseline: 17.1112x; 1.3529x over previous
#include <cuda_runtime.h>
#include <cuda_bf16.h>
#include <mma.h>
#include <cstdint>

using namespace nvcuda;

#define NN 50000
#define NE 800000
#define D 128
#define NB 148
#define NT 512
#define GS (NB * NT)
#define NWARPS (NT / 32)
#define CHUNK ((NN + NB - 1) / NB)   // 338 nodes per block
#define NTILES ((NN + 127) / 128)    // 391
#define LDA 136                       // bf16 leading dim (padded)
#define LDS_ 132                      // f32 staging leading dim (padded)
#define BUF_BYTES (128 * LDA * 2)     // 34816 bytes per bf16 buffer

typedef unsigned long long u64;

// -------- device scratch (no runtime allocation allowed) --------
__device__ unsigned g_gen = 0;
__device__ unsigned g_arrive = 0;
__device__ int   g_cnt[NN];          // zero-init; reset each pass
__device__ int   g_off[NN + 1];
__device__ int   g_pos[NN];
__device__ int   g_srcs[NE];
__device__ int   g_bsum[NB];
__device__ float g_mean[NN * D];
__device__ float g_h0[NN * D];
__device__ float g_h1[NN * D];
__device__ float g_ps[NB * D];
__device__ float g_ps2[NB * D];

// -------- grid-wide software barrier (all NB blocks co-resident) --------
__device__ __forceinline__ void gbar() {
    __syncthreads();
    if (threadIdx.x == 0) {
        __threadfence();
        unsigned gen = atomicAdd(&g_gen, 0u);
        unsigned arrived = atomicAdd(&g_arrive, 1u) + 1u;
        if (arrived == NB) {
            atomicExch(&g_arrive, 0u);
            __threadfence();
            atomicAdd(&g_gen, 1u);
        } else {
            while (atomicAdd(&g_gen, 0u) == gen) { __nanosleep(128); }
        }
        __threadfence();
    }
    __syncthreads();
}

// -------- mean aggregation: one warp per node --------
__device__ __forceinline__ void agg_phase(const float* __restrict__ h,
                                          float* __restrict__ o) {
    const int lane = threadIdx.x & 31;
    const int warp = threadIdx.x >> 5;
    const int gw0 = blockIdx.x * NWARPS + warp;
    for (int n = gw0; n < NN; n += NB * NWARPS) {
        int beg = g_off[n];
        int end = g_off[n + 1];
        float4 a0 = make_float4(0.f, 0.f, 0.f, 0.f);
        float4 a1 = make_float4(0.f, 0.f, 0.f, 0.f);
        int i = beg;
        for (; i + 7 < end; i += 8) {
            int s0 = __ldg(&g_srcs[i]);
            int s1 = __ldg(&g_srcs[i + 1]);
            int s2 = __ldg(&g_srcs[i + 2]);
            int s3 = __ldg(&g_srcs[i + 3]);
            int s4 = __ldg(&g_srcs[i + 4]);
            int s5 = __ldg(&g_srcs[i + 5]);
            int s6 = __ldg(&g_srcs[i + 6]);
            int s7 = __ldg(&g_srcs[i + 7]);
            float4 v0 = __ldg((const float4*)(h + s0 * D + lane * 4));
            float4 v1 = __ldg((const float4*)(h + s1 * D + lane * 4));
            float4 v2 = __ldg((const float4*)(h + s2 * D + lane * 4));
            float4 v3 = __ldg((const float4*)(h + s3 * D + lane * 4));
            float4 v4 = __ldg((const float4*)(h + s4 * D + lane * 4));
            float4 v5 = __ldg((const float4*)(h + s5 * D + lane * 4));
            float4 v6 = __ldg((const float4*)(h + s6 * D + lane * 4));
            float4 v7 = __ldg((const float4*)(h + s7 * D + lane * 4));
            a0.x += (v0.x + v1.x) + (v2.x + v3.x);
            a0.y += (v0.y + v1.y) + (v2.y + v3.y);
            a0.z += (v0.z + v1.z) + (v2.z + v3.z);
            a0.w += (v0.w + v1.w) + (v2.w + v3.w);
            a1.x += (v4.x + v5.x) + (v6.x + v7.x);
            a1.y += (v4.y + v5.y) + (v6.y + v7.y);
            a1.z += (v4.z + v5.z) + (v6.z + v7.z);
            a1.w += (v4.w + v5.w) + (v6.w + v7.w);
        }
        for (; i < end; i++) {
            int s0 = __ldg(&g_srcs[i]);
            float4 v0 = __ldg((const float4*)(h + s0 * D + lane * 4));
            a0.x += v0.x; a0.y += v0.y; a0.z += v0.z; a0.w += v0.w;
        }
        float inv = 1.0f / fmaxf((float)(end - beg), 1.0f);
        float4 r;
        r.x = (a0.x + a1.x) * inv;
        r.y = (a0.y + a1.y) * inv;
        r.z = (a0.z + a1.z) * inv;
        r.w = (a0.w + a1.w) * inv;
        *(float4*)(o + n * D + lane * 4) = r;
    }
}

// -------- bf16x2 pack: low half = first arg --------
__device__ __forceinline__ uint32_t cvt2(float lo, float hi) {
    uint32_t r;
    asm("cvt.rn.bf16x2.f32 %0, %1, %2;" : "=r"(r) : "f"(hi), "f"(lo));
    return r;
}

// -------- fp32 -> split bf16 (hi/lo), row-major ld=LDA --------
__device__ __forceinline__ void conv_split(const float* __restrict__ S,
                                           int row0, int rmax,
                                           __nv_bfloat16* __restrict__ dhi,
                                           __nv_bfloat16* __restrict__ dlo) {
#pragma unroll
    for (int it = 0; it < 8; it++) {
        int idx = threadIdx.x + it * NT;     // 0..4095 quads
        int r = idx >> 5;                    // 0..127
        int kq = idx & 31;                   // quad along k
        int row = row0 + r;
        float4 v = make_float4(0.f, 0.f, 0.f, 0.f);
        if (row < rmax) v = *(const float4*)(S + (size_t)row * D + kq * 4);
        uint32_t h0 = cvt2(v.x, v.y);
        uint32_t h1 = cvt2(v.z, v.w);
        uint32_t l0 = cvt2(v.x - __uint_as_float(h0 << 16),
                           v.y - __uint_as_float(h0 & 0xffff0000u));
        uint32_t l1 = cvt2(v.z - __uint_as_float(h1 << 16),
                           v.w - __uint_as_float(h1 & 0xffff0000u));
        int off = r * LDA + kq * 4;
        *(uint2*)(dhi + off) = make_uint2(h0, h1);
        *(uint2*)(dlo + off) = make_uint2(l0, l1);
    }
}

// -------- tensor-core (HMMA/wmma) fused dual GEMM ----
// out = A0@Wl^T + A1@Wr^T + bias [relu], split-bf16 3-product emulation.
__device__ __forceinline__ void gemm_wmma(const float* __restrict__ A0,
                                          const float* __restrict__ A1,
                                          const float* __restrict__ Wl,
                                          const float* __restrict__ Wr,
                                          const float* __restrict__ bias,
                                          float* __restrict__ out,
                                          bool relu, char* base) {
    __nv_bfloat16* wlh = (__nv_bfloat16*)(base);
    __nv_bfloat16* wll = (__nv_bfloat16*)(base + BUF_BYTES);
    __nv_bfloat16* wrh = (__nv_bfloat16*)(base + 2 * BUF_BYTES);
    __nv_bfloat16* wrl = (__nv_bfloat16*)(base + 3 * BUF_BYTES);
    __nv_bfloat16* ahi = (__nv_bfloat16*)(base + 4 * BUF_BYTES);
    __nv_bfloat16* alo = (__nv_bfloat16*)(base + 5 * BUF_BYTES);
    float* staging = (float*)(base + 4 * BUF_BYTES);  // reuses ahi+alo

    const int tid = threadIdx.x;
    const int warp = tid >> 5;
    const int wr_ = warp >> 2;   // warp row 0..3 (rows wr_*32)
    const int wc_ = warp & 3;    // warp col 0..3 (cols wc_*32)

    // convert both weight matrices once (resident across tiles)
    conv_split(Wl, 0, D, wlh, wll);
    conv_split(Wr, 0, D, wrh, wrl);
    __syncthreads();

    for (int t = blockIdx.x; t < NTILES; t += NB) {
        const int row0 = t * 128;

        wmma::fragment<wmma::accumulator, 16, 16, 16, float> fc[2][2];
#pragma unroll
        for (int i = 0; i < 2; i++)
#pragma unroll
            for (int j = 0; j < 2; j++) wmma::fill_fragment(fc[i][j], 0.f);

#pragma unroll
        for (int ph = 0; ph < 2; ph++) {
            conv_split(ph ? A1 : A0, row0, NN, ahi, alo);
            __syncthreads();
            const __nv_bfloat16* wh = ph ? wrh : wlh;
            const __nv_bfloat16* wl = ph ? wrl : wll;

#pragma unroll
            for (int ks = 0; ks < 8; ks++) {
                wmma::fragment<wmma::matrix_a, 16, 16, 16, __nv_bfloat16,
                               wmma::row_major> fa_hi[2], fa_lo[2];
                wmma::fragment<wmma::matrix_b, 16, 16, 16, __nv_bfloat16,
                               wmma::col_major> fb_hi[2], fb_lo[2];
#pragma unroll
                for (int i = 0; i < 2; i++) {
                    const int r = wr_ * 32 + i * 16;
                    wmma::load_matrix_sync(fa_hi[i], ahi + r * LDA + ks * 16, LDA);
                    wmma::load_matrix_sync(fa_lo[i], alo + r * LDA + ks * 16, LDA);
                }
#pragma unroll
                for (int j = 0; j < 2; j++) {
                    const int c = wc_ * 32 + j * 16;
                    wmma::load_matrix_sync(fb_hi[j], wh + c * LDA + ks * 16, LDA);
                    wmma::load_matrix_sync(fb_lo[j], wl + c * LDA + ks * 16, LDA);
                }
#pragma unroll
                for (int i = 0; i < 2; i++)
#pragma unroll
                    for (int j = 0; j < 2; j++) {
                        wmma::mma_sync(fc[i][j], fa_hi[i], fb_hi[j], fc[i][j]);
                        wmma::mma_sync(fc[i][j], fa_hi[i], fb_lo[j], fc[i][j]);
                        wmma::mma_sync(fc[i][j], fa_lo[i], fb_hi[j], fc[i][j]);
                    }
            }
            __syncthreads();  // done reading ahi/alo before next phase/staging
        }

        // stage accumulators to smem (reuses ahi/alo area)
#pragma unroll
        for (int i = 0; i < 2; i++)
#pragma unroll
            for (int j = 0; j < 2; j++)
                wmma::store_matrix_sync(
                    staging + (wr_ * 32 + i * 16) * LDS_ + wc_ * 32 + j * 16,
                    fc[i][j], LDS_, wmma::mem_row_major);
        __syncthreads();

        // bias + relu + global store
#pragma unroll
        for (int it = 0; it < 8; it++) {
            int idx = tid + it * NT;    // 0..4095 float4 slots
            int r = idx >> 5;
            int cq = idx & 31;
            int row = row0 + r;
            if (row < NN) {
                float4 v = *(const float4*)(staging + r * LDS_ + cq * 4);
                float4 b4 = *(const float4*)(bias + cq * 4);
                v.x += b4.x; v.y += b4.y; v.z += b4.z; v.w += b4.w;
                if (relu) {
                    v.x = fmaxf(v.x, 0.f); v.y = fmaxf(v.y, 0.f);
                    v.z = fmaxf(v.z, 0.f); v.w = fmaxf(v.w, 0.f);
                }
                *(float4*)(out + (size_t)row * D + cq * 4) = v;
            }
        }
        __syncthreads();  // staging reads done before next tile's conv_split
    }
}

// -------- the mono-kernel --------
__global__ void __launch_bounds__(NT, 1)
mono_kernel(const float* __restrict__ x,
            const int* __restrict__ src, const int* __restrict__ dst,
            const float* __restrict__ Wl0, const float* __restrict__ bl0,
            const float* __restrict__ Wr0,
            const float* __restrict__ Wl1, const float* __restrict__ bl1,
            const float* __restrict__ Wr1,
            const float* __restrict__ Wl2, const float* __restrict__ bl2,
            const float* __restrict__ Wr2,
            const float* __restrict__ gamma, const float* __restrict__ beta,
            float* __restrict__ out) {
    extern __shared__ char smc[];
    char* base = (char*)(((uintptr_t)smc + 1023) & ~(uintptr_t)1023);
    const int tid = threadIdx.x;
    const int bid = blockIdx.x;
    const int gt = bid * NT + tid;
    const int lane = tid & 31;
    const int warp = tid >> 5;

    // ---- phase 1: histogram of dst ----
    for (int e = gt; e < NE; e += GS) atomicAdd(&g_cnt[dst[e]], 1);
    gbar();

    // ---- phase 2: per-block chunk sums ----
    {
        __shared__ int red[NWARPS];
        int cb = bid * CHUNK;
        int v = 0;
        for (int i = tid; i < CHUNK; i += NT) {
            int idx = cb + i;
            if (idx < NN) v += g_cnt[idx];
        }
#pragma unroll
        for (int o = 16; o > 0; o >>= 1) v += __shfl_down_sync(0xffffffffu, v, o);
        if (lane == 0) red[warp] = v;
        __syncthreads();
        if (warp == 0) {
            int w = (lane < NWARPS) ? red[lane] : 0;
#pragma unroll
            for (int o = 8; o > 0; o >>= 1) w += __shfl_down_sync(0xffffffffu, w, o);
            if (lane == 0) g_bsum[bid] = w;
        }
    }
    gbar();

    // ---- phase 3: every block scans block sums locally ----
    __shared__ int s_boff;
    {
        __shared__ int sb[NB];
        if (tid < NB) sb[tid] = g_bsum[tid];
        __syncthreads();
        if (tid == 0) {
            int run = 0;
            for (int b = 0; b < NB; b++) { int v = sb[b]; sb[b] = run; run += v; }
            s_boff = sb[bid];
        }
        __syncthreads();
        if (bid == NB - 1 && tid == 0) g_off[NN] = NE;
    }

    // ---- phase 4: write offsets (block scan of chunk), reset g_cnt ----
    {
        __shared__ int wsum[NWARPS];
        int cb = bid * CHUNK;
        int idx = cb + tid;
        int v = (tid < CHUNK && idx < NN) ? g_cnt[idx] : 0;
        int inc = v;
#pragma unroll
        for (int o = 1; o < 32; o <<= 1) {
            int u = __shfl_up_sync(0xffffffffu, inc, o);
            if (lane >= o) inc += u;
        }
        if (lane == 31) wsum[warp] = inc;
        __syncthreads();
        if (warp == 0) {
            int w = (lane < NWARPS) ? wsum[lane] : 0;
            int wi = w;
#pragma unroll
            for (int o = 1; o < NWARPS; o <<= 1) {
                int u = __shfl_up_sync(0xffffffffu, wi, o);
                if (lane >= o) wi += u;
            }
            if (lane < NWARPS) wsum[lane] = wi - w;
        }
        __syncthreads();
        int excl = s_boff + wsum[warp] + inc - v;
        if (tid < CHUNK && idx < NN) {
            g_off[idx] = excl;
            g_pos[idx] = excl;
            g_cnt[idx] = 0;   // reset for next graph replay
        }
    }
    gbar();

    // ---- phase 5: scatter src by dst ----
    for (int e = gt; e < NE; e += GS) {
        int p = atomicAdd(&g_pos[dst[e]], 1);
        g_srcs[p] = src[e];
    }
    gbar();

    // ---- layer 0 ----
    agg_phase(x, g_mean);
    gbar();
    gemm_wmma(g_mean, x, Wl0, Wr0, bl0, g_h0, true, base);
    gbar();

    // ---- layer 1 ----
    agg_phase(g_h0, g_mean);
    gbar();
    gemm_wmma(g_mean, g_h0, Wl1, Wr1, bl1, g_h1, false, base);
    gbar();

    // ---- batchnorm stats (per-block partials) ----
    {
        float* smf = (float*)base;
        int col = tid & 127;
        int rg = tid >> 7;
        int cb = bid * CHUNK;
        int lim = min(cb + CHUNK, NN);
        float s = 0.f, s2 = 0.f;
        for (int r = cb + rg; r < lim; r += 4) {
            float v = g_h1[r * D + col];
            s += v;
            s2 += v * v;
        }
        __syncthreads();
        smf[rg * 128 + col] = s;
        smf[512 + rg * 128 + col] = s2;
        __syncthreads();
        if (rg == 0) {
            float ts = smf[col] + smf[128 + col] + smf[256 + col] + smf[384 + col];
            float t2 = smf[512 + col] + smf[640 + col] + smf[768 + col] + smf[896 + col];
            g_ps[bid * D + col] = ts;
            g_ps2[bid * D + col] = t2;
        }
    }
    gbar();

    // ---- batchnorm finalize (replicated per block) + apply + relu ----
    {
        __shared__ float s_scale[D], s_shift[D];
        __shared__ float r1[NT], r2[NT];
        int col = tid & 127;
        int part = tid >> 7;
        float s = 0.f, s2 = 0.f;
        for (int b = part; b < NB; b += 4) {
            s += g_ps[b * D + col];
            s2 += g_ps2[b * D + col];
        }
        r1[tid] = s; r2[tid] = s2;
        __syncthreads();
        if (part == 0) {
            double S = (double)r1[col] + (double)r1[col + 128] +
                       (double)r1[col + 256] + (double)r1[col + 384];
            double S2 = (double)r2[col] + (double)r2[col + 128] +
                        (double)r2[col + 256] + (double)r2[col + 384];
            double mu = S / (double)NN;
            double var = S2 / (double)NN - mu * mu;
            float inv = rsqrtf((float)var + 1e-5f);
            float sc = inv * gamma[col];
            s_scale[col] = sc;
            s_shift[col] = beta[col] - (float)mu * sc;
        }
        __syncthreads();
        for (int i = gt; i < NN * (D / 4); i += GS) {
            float4 v = ((float4*)g_h1)[i];
            int c = (i & 31) * 4;
            v.x = fmaxf(fmaf(v.x, s_scale[c + 0], s_shift[c + 0]), 0.f);
            v.y = fmaxf(fmaf(v.y, s_scale[c + 1], s_shift[c + 1]), 0.f);
            v.z = fmaxf(fmaf(v.z, s_scale[c + 2], s_shift[c + 2]), 0.f);
            v.w = fmaxf(fmaf(v.w, s_scale[c + 3], s_shift[c + 3]), 0.f);
            ((float4*)g_h1)[i] = v;
        }
    }
    gbar();

    // ---- layer 2 ----
    agg_phase(g_h1, g_mean);
    gbar();
    gemm_wmma(g_mean, g_h1, Wl2, Wr2, bl2, out, false, base);
}

// -------- launch --------
extern "C" void kernel_launch(void* const* d_in, const int* in_sizes, int n_in,
                              void* d_out, int out_size) {
    const float* x     = (const float*)d_in[0];
    const int*   ei    = (const int*)d_in[1];
    const float* Wl0   = (const float*)d_in[2];
    const float* bl0   = (const float*)d_in[3];
    const float* Wr0   = (const float*)d_in[4];
    const float* Wl1   = (const float*)d_in[5];
    const float* bl1   = (const float*)d_in[6];
    const float* Wr1   = (const float*)d_in[7];
    const float* Wl2   = (const float*)d_in[8];
    const float* bl2   = (const float*)d_in[9];
    const float* Wr2   = (const float*)d_in[10];
    const float* gamma = (const float*)d_in[11];
    const float* beta  = (const float*)d_in[12];
    float* out = (float*)d_out;

    const int* srcp = ei;
    const int* dstp = ei + NE;

    const int SMEM = 6 * BUF_BYTES + 1024;  // 6 x 34816 + align slack = 209920
    static bool attr_set = false;
    if (!attr_set) {
        cudaFuncSetAttribute(mono_kernel,
                             cudaFuncAttributeMaxDynamicSharedMemorySize, SMEM);
        attr_set = true;
    }

    mono_kernel<<<NB, NT, SMEM>>>(x, srcp, dstp,
                                  Wl0, bl0, Wr0,
                                  Wl1, bl1, Wr1,
                                  Wl2, bl2, Wr2,
                                  gamma, beta, out);
}

// round 9
// speedup vs baseline: 17.7975x; 1.0401x over previous
#include <cuda_runtime.h>
#include <cuda_bf16.h>
#include <cuda_fp16.h>
#include <mma.h>
#include <cstdint>

using namespace nvcuda;

#define NN 50000
#define NE 800000
#define D 128
#define NB 148
#define NT 512
#define GS (NB * NT)
#define NWARPS (NT / 32)
#define CHUNK ((NN + NB - 1) / NB)   // 338 nodes per block
#define NTILES ((NN + 127) / 128)    // 391
#define LDA 136                       // bf16 smem leading dim (padded)
#define LDS_ 132                      // f32 staging leading dim (padded)
#define BUF_BYTES (128 * LDA * 2)     // 34816 bytes per bf16 smem buffer

typedef unsigned long long u64;

// -------- device scratch (no runtime allocation allowed) --------
__device__ unsigned g_gen = 0;
__device__ unsigned g_arrive = 0;
__device__ int   g_cnt[NN];
__device__ int   g_off[NN + 1];
__device__ int   g_pos[NN];
__device__ int   g_srcs[NE];
__device__ int   g_bsum[NB];
__device__ float g_ps[NB * D];
__device__ float g_ps2[NB * D];
// split-bf16 + fp16 feature buffers
__device__ __nv_bfloat16 g_xh[NN * D];
__device__ __nv_bfloat16 g_xl[NN * D];
__device__ __half        g_x16[NN * D];
__device__ __nv_bfloat16 g_mh[NN * D];
__device__ __nv_bfloat16 g_ml[NN * D];
__device__ __nv_bfloat16 g_h0h[NN * D];
__device__ __nv_bfloat16 g_h0l[NN * D];
__device__ __half        g_h016[NN * D];
__device__ __nv_bfloat16 g_h1h[NN * D];
__device__ __nv_bfloat16 g_h1l[NN * D];
__device__ __half        g_h116[NN * D];

// -------- helpers --------
__device__ __forceinline__ uint32_t cvt2(float lo, float hi) {
    uint32_t r;
    asm("cvt.rn.bf16x2.f32 %0, %1, %2;" : "=r"(r) : "f"(hi), "f"(lo));
    return r;
}
__device__ __forceinline__ void split4(float4 v, uint2& h, uint2& l) {
    uint32_t h0 = cvt2(v.x, v.y);
    uint32_t h1 = cvt2(v.z, v.w);
    uint32_t l0 = cvt2(v.x - __uint_as_float(h0 << 16),
                       v.y - __uint_as_float(h0 & 0xffff0000u));
    uint32_t l1 = cvt2(v.z - __uint_as_float(h1 << 16),
                       v.w - __uint_as_float(h1 & 0xffff0000u));
    h = make_uint2(h0, h1);
    l = make_uint2(l0, l1);
}
__device__ __forceinline__ uint2 half4(float4 v) {
    uint2 r;
    *(__half2*)&r.x = __floats2half2_rn(v.x, v.y);
    *(__half2*)&r.y = __floats2half2_rn(v.z, v.w);
    return r;
}
__device__ __forceinline__ float4 rec4(uint2 h, uint2 l) {
    float4 v;
    v.x = __uint_as_float(h.x << 16) + __uint_as_float(l.x << 16);
    v.y = __uint_as_float(h.x & 0xffff0000u) + __uint_as_float(l.x & 0xffff0000u);
    v.z = __uint_as_float(h.y << 16) + __uint_as_float(l.y << 16);
    v.w = __uint_as_float(h.y & 0xffff0000u) + __uint_as_float(l.y & 0xffff0000u);
    return v;
}

// -------- grid-wide software barrier --------
__device__ __forceinline__ void gbar() {
    __syncthreads();
    if (threadIdx.x == 0) {
        __threadfence();
        unsigned gen = atomicAdd(&g_gen, 0u);
        unsigned arrived = atomicAdd(&g_arrive, 1u) + 1u;
        if (arrived == NB) {
            atomicExch(&g_arrive, 0u);
            __threadfence();
            atomicAdd(&g_gen, 1u);
        } else {
            while (atomicAdd(&g_gen, 0u) == gen) { __nanosleep(128); }
        }
        __threadfence();
    }
    __syncthreads();
}

// -------- mean aggregation: fp16 gather, split-bf16 mean output --------
__device__ __forceinline__ void agg_phase(const __half* __restrict__ h16) {
    const int lane = threadIdx.x & 31;
    const int warp = threadIdx.x >> 5;
    const int gw0 = blockIdx.x * NWARPS + warp;
    for (int n = gw0; n < NN; n += NB * NWARPS) {
        int beg = g_off[n];
        int end = g_off[n + 1];
        float4 a0 = make_float4(0.f, 0.f, 0.f, 0.f);
        float4 a1 = make_float4(0.f, 0.f, 0.f, 0.f);
        int i = beg;
        for (; i + 7 < end; i += 8) {
            int s0 = __ldg(&g_srcs[i]);
            int s1 = __ldg(&g_srcs[i + 1]);
            int s2 = __ldg(&g_srcs[i + 2]);
            int s3 = __ldg(&g_srcs[i + 3]);
            int s4 = __ldg(&g_srcs[i + 4]);
            int s5 = __ldg(&g_srcs[i + 5]);
            int s6 = __ldg(&g_srcs[i + 6]);
            int s7 = __ldg(&g_srcs[i + 7]);
            uint2 u0 = __ldg((const uint2*)(h16 + (size_t)s0 * D + lane * 4));
            uint2 u1 = __ldg((const uint2*)(h16 + (size_t)s1 * D + lane * 4));
            uint2 u2 = __ldg((const uint2*)(h16 + (size_t)s2 * D + lane * 4));
            uint2 u3 = __ldg((const uint2*)(h16 + (size_t)s3 * D + lane * 4));
            uint2 u4 = __ldg((const uint2*)(h16 + (size_t)s4 * D + lane * 4));
            uint2 u5 = __ldg((const uint2*)(h16 + (size_t)s5 * D + lane * 4));
            uint2 u6 = __ldg((const uint2*)(h16 + (size_t)s6 * D + lane * 4));
            uint2 u7 = __ldg((const uint2*)(h16 + (size_t)s7 * D + lane * 4));
#define ACC(acc, u) do { \
            float2 p = __half22float2(*(const __half2*)&(u).x); \
            float2 q = __half22float2(*(const __half2*)&(u).y); \
            (acc).x += p.x; (acc).y += p.y; (acc).z += q.x; (acc).w += q.y; } while (0)
            ACC(a0, u0); ACC(a0, u1); ACC(a0, u2); ACC(a0, u3);
            ACC(a1, u4); ACC(a1, u5); ACC(a1, u6); ACC(a1, u7);
        }
        for (; i < end; i++) {
            int s0 = __ldg(&g_srcs[i]);
            uint2 u0 = __ldg((const uint2*)(h16 + (size_t)s0 * D + lane * 4));
            ACC(a0, u0);
        }
#undef ACC
        float inv = 1.0f / fmaxf((float)(end - beg), 1.0f);
        float4 r;
        r.x = (a0.x + a1.x) * inv;
        r.y = (a0.y + a1.y) * inv;
        r.z = (a0.z + a1.z) * inv;
        r.w = (a0.w + a1.w) * inv;
        uint2 hh, ll;
        split4(r, hh, ll);
        *(uint2*)(g_mh + (size_t)n * D + lane * 4) = hh;
        *(uint2*)(g_ml + (size_t)n * D + lane * 4) = ll;
    }
}

// -------- fp32 W -> split bf16 smem (padded), once per GEMM call --------
__device__ __forceinline__ void conv_w(const float* __restrict__ S,
                                       __nv_bfloat16* __restrict__ dhi,
                                       __nv_bfloat16* __restrict__ dlo) {
#pragma unroll
    for (int it = 0; it < 8; it++) {
        int idx = threadIdx.x + it * NT;     // 0..4095 quads
        int r = idx >> 5;
        int kq = idx & 31;
        float4 v = *(const float4*)(S + (size_t)r * D + kq * 4);
        uint2 h, l;
        split4(v, h, l);
        int off = r * LDA + kq * 4;
        *(uint2*)(dhi + off) = h;
        *(uint2*)(dlo + off) = l;
    }
}

// -------- tensor-core fused dual GEMM, pre-split A from gmem ----
// out = A0@Wl^T + A1@Wr^T + bias. MODE 0: relu -> (oh,ol,o16)
// MODE 1: -> (oh,ol).  MODE 2: -> fp32 outf.
template <int MODE>
__device__ __forceinline__ void gemm_wmma(
    const __nv_bfloat16* __restrict__ a0h, const __nv_bfloat16* __restrict__ a0l,
    const __nv_bfloat16* __restrict__ a1h, const __nv_bfloat16* __restrict__ a1l,
    const float* __restrict__ Wl, const float* __restrict__ Wr,
    const float* __restrict__ bias,
    float* __restrict__ outf,
    __nv_bfloat16* __restrict__ oh, __nv_bfloat16* __restrict__ ol,
    __half* __restrict__ o16, char* base) {
    __nv_bfloat16* wlh = (__nv_bfloat16*)(base);
    __nv_bfloat16* wll = (__nv_bfloat16*)(base + BUF_BYTES);
    __nv_bfloat16* wrh = (__nv_bfloat16*)(base + 2 * BUF_BYTES);
    __nv_bfloat16* wrl = (__nv_bfloat16*)(base + 3 * BUF_BYTES);
    __nv_bfloat16* ahi = (__nv_bfloat16*)(base + 4 * BUF_BYTES);
    __nv_bfloat16* alo = (__nv_bfloat16*)(base + 5 * BUF_BYTES);
    float* staging = (float*)(base + 4 * BUF_BYTES);  // reuses ahi+alo

    const int tid = threadIdx.x;
    const int warp = tid >> 5;
    const int wr_ = warp >> 2;
    const int wc_ = warp & 3;

    conv_w(Wl, wlh, wll);
    conv_w(Wr, wrh, wrl);
    __syncthreads();

    for (int t = blockIdx.x; t < NTILES; t += NB) {
        const int row0 = t * 128;

        wmma::fragment<wmma::accumulator, 16, 16, 16, float> fc[2][2];
#pragma unroll
        for (int i = 0; i < 2; i++)
#pragma unroll
            for (int j = 0; j < 2; j++) wmma::fill_fragment(fc[i][j], 0.f);

#pragma unroll
        for (int ph = 0; ph < 2; ph++) {
            const __nv_bfloat16* Ah = ph ? a1h : a0h;
            const __nv_bfloat16* Al = ph ? a1l : a0l;
            // copy pre-split tile into padded smem (16B granules)
#pragma unroll
            for (int it = 0; it < 4; it++) {
                int idx = tid + it * NT;      // 0..2047
                int r = idx >> 4;             // 16 granules of 16B per row
                int g = idx & 15;
                int row = row0 + r;
                uint4 vh = make_uint4(0, 0, 0, 0), vl = make_uint4(0, 0, 0, 0);
                if (row < NN) {
                    vh = __ldg((const uint4*)(Ah + (size_t)row * D + g * 8));
                    vl = __ldg((const uint4*)(Al + (size_t)row * D + g * 8));
                }
                *(uint4*)(ahi + r * LDA + g * 8) = vh;
                *(uint4*)(alo + r * LDA + g * 8) = vl;
            }
            __syncthreads();
            const __nv_bfloat16* wh = ph ? wrh : wlh;
            const __nv_bfloat16* wl = ph ? wrl : wll;

#pragma unroll
            for (int ks = 0; ks < 8; ks++) {
                wmma::fragment<wmma::matrix_a, 16, 16, 16, __nv_bfloat16,
                               wmma::row_major> fa_hi[2], fa_lo[2];
                wmma::fragment<wmma::matrix_b, 16, 16, 16, __nv_bfloat16,
                               wmma::col_major> fb_hi[2], fb_lo[2];
#pragma unroll
                for (int i = 0; i < 2; i++) {
                    const int r = wr_ * 32 + i * 16;
                    wmma::load_matrix_sync(fa_hi[i], ahi + r * LDA + ks * 16, LDA);
                    wmma::load_matrix_sync(fa_lo[i], alo + r * LDA + ks * 16, LDA);
                }
#pragma unroll
                for (int j = 0; j < 2; j++) {
                    const int c = wc_ * 32 + j * 16;
                    wmma::load_matrix_sync(fb_hi[j], wh + c * LDA + ks * 16, LDA);
                    wmma::load_matrix_sync(fb_lo[j], wl + c * LDA + ks * 16, LDA);
                }
#pragma unroll
                for (int i = 0; i < 2; i++)
#pragma unroll
                    for (int j = 0; j < 2; j++) {
                        wmma::mma_sync(fc[i][j], fa_hi[i], fb_hi[j], fc[i][j]);
                        wmma::mma_sync(fc[i][j], fa_hi[i], fb_lo[j], fc[i][j]);
                        wmma::mma_sync(fc[i][j], fa_lo[i], fb_hi[j], fc[i][j]);
                    }
            }
            __syncthreads();
        }

        // stage accumulators to smem (reuses ahi/alo area)
#pragma unroll
        for (int i = 0; i < 2; i++)
#pragma unroll
            for (int j = 0; j < 2; j++)
                wmma::store_matrix_sync(
                    staging + (wr_ * 32 + i * 16) * LDS_ + wc_ * 32 + j * 16,
                    fc[i][j], LDS_, wmma::mem_row_major);
        __syncthreads();

        // epilogue
#pragma unroll
        for (int it = 0; it < 8; it++) {
            int idx = tid + it * NT;
            int r = idx >> 5;
            int cq = idx & 31;
            int row = row0 + r;
            if (row < NN) {
                float4 v = *(const float4*)(staging + r * LDS_ + cq * 4);
                float4 b4 = *(const float4*)(bias + cq * 4);
                v.x += b4.x; v.y += b4.y; v.z += b4.z; v.w += b4.w;
                size_t off = (size_t)row * D + cq * 4;
                if (MODE == 0) {
                    v.x = fmaxf(v.x, 0.f); v.y = fmaxf(v.y, 0.f);
                    v.z = fmaxf(v.z, 0.f); v.w = fmaxf(v.w, 0.f);
                    uint2 hh, ll;
                    split4(v, hh, ll);
                    *(uint2*)(oh + off) = hh;
                    *(uint2*)(ol + off) = ll;
                    *(uint2*)(o16 + off) = half4(v);
                } else if (MODE == 1) {
                    uint2 hh, ll;
                    split4(v, hh, ll);
                    *(uint2*)(oh + off) = hh;
                    *(uint2*)(ol + off) = ll;
                } else {
                    *(float4*)(outf + off) = v;
                }
            }
        }
        __syncthreads();
    }
}

// -------- the mono-kernel --------
__global__ void __launch_bounds__(NT, 1)
mono_kernel(const float* __restrict__ x,
            const int* __restrict__ src, const int* __restrict__ dst,
            const float* __restrict__ Wl0, const float* __restrict__ bl0,
            const float* __restrict__ Wr0,
            const float* __restrict__ Wl1, const float* __restrict__ bl1,
            const float* __restrict__ Wr1,
            const float* __restrict__ Wl2, const float* __restrict__ bl2,
            const float* __restrict__ Wr2,
            const float* __restrict__ gamma, const float* __restrict__ beta,
            float* __restrict__ out) {
    extern __shared__ char smc[];
    char* base = (char*)(((uintptr_t)smc + 1023) & ~(uintptr_t)1023);
    const int tid = threadIdx.x;
    const int bid = blockIdx.x;
    const int gt = bid * NT + tid;
    const int lane = tid & 31;
    const int warp = tid >> 5;

    // ---- phase 1: histogram of dst + split/convert x ----
    for (int e = gt; e < NE; e += GS) atomicAdd(&g_cnt[dst[e]], 1);
    for (int i = gt; i < NN * 32; i += GS) {
        float4 v = __ldg((const float4*)(x + (size_t)i * 4));
        uint2 h, l;
        split4(v, h, l);
        ((uint2*)g_xh)[i] = h;
        ((uint2*)g_xl)[i] = l;
        ((uint2*)g_x16)[i] = half4(v);
    }
    gbar();

    // ---- phase 2: per-block chunk sums ----
    {
        __shared__ int red[NWARPS];
        int cb = bid * CHUNK;
        int v = 0;
        for (int i = tid; i < CHUNK; i += NT) {
            int idx = cb + i;
            if (idx < NN) v += g_cnt[idx];
        }
#pragma unroll
        for (int o = 16; o > 0; o >>= 1) v += __shfl_down_sync(0xffffffffu, v, o);
        if (lane == 0) red[warp] = v;
        __syncthreads();
        if (warp == 0) {
            int w = (lane < NWARPS) ? red[lane] : 0;
#pragma unroll
            for (int o = 8; o > 0; o >>= 1) w += __shfl_down_sync(0xffffffffu, w, o);
            if (lane == 0) g_bsum[bid] = w;
        }
    }
    gbar();

    // ---- phase 3: every block scans block sums locally ----
    __shared__ int s_boff;
    {
        __shared__ int sb[NB];
        if (tid < NB) sb[tid] = g_bsum[tid];
        __syncthreads();
        if (tid == 0) {
            int run = 0;
            for (int b = 0; b < NB; b++) { int v = sb[b]; sb[b] = run; run += v; }
            s_boff = sb[bid];
        }
        __syncthreads();
        if (bid == NB - 1 && tid == 0) g_off[NN] = NE;
    }

    // ---- phase 4: write offsets, reset g_cnt ----
    {
        __shared__ int wsum[NWARPS];
        int cb = bid * CHUNK;
        int idx = cb + tid;
        int v = (tid < CHUNK && idx < NN) ? g_cnt[idx] : 0;
        int inc = v;
#pragma unroll
        for (int o = 1; o < 32; o <<= 1) {
            int u = __shfl_up_sync(0xffffffffu, inc, o);
            if (lane >= o) inc += u;
        }
        if (lane == 31) wsum[warp] = inc;
        __syncthreads();
        if (warp == 0) {
            int w = (lane < NWARPS) ? wsum[lane] : 0;
            int wi = w;
#pragma unroll
            for (int o = 1; o < NWARPS; o <<= 1) {
                int u = __shfl_up_sync(0xffffffffu, wi, o);
                if (lane >= o) wi += u;
            }
            if (lane < NWARPS) wsum[lane] = wi - w;
        }
        __syncthreads();
        int excl = s_boff + wsum[warp] + inc - v;
        if (tid < CHUNK && idx < NN) {
            g_off[idx] = excl;
            g_pos[idx] = excl;
            g_cnt[idx] = 0;
        }
    }
    gbar();

    // ---- phase 5: scatter src by dst ----
    for (int e = gt; e < NE; e += GS) {
        int p = atomicAdd(&g_pos[dst[e]], 1);
        g_srcs[p] = src[e];
    }
    gbar();

    // ---- layer 0 ----
    agg_phase(g_x16);
    gbar();
    gemm_wmma<0>(g_mh, g_ml, g_xh, g_xl, Wl0, Wr0, bl0,
                 nullptr, g_h0h, g_h0l, g_h016, base);
    gbar();

    // ---- layer 1 ----
    agg_phase(g_h016);
    gbar();
    gemm_wmma<1>(g_mh, g_ml, g_h0h, g_h0l, Wl1, Wr1, bl1,
                 nullptr, g_h1h, g_h1l, nullptr, base);
    gbar();

    // ---- batchnorm stats ----
    {
        float4* smf = (float4*)base;
        int q = tid & 31;
        int rg = tid >> 5;  // 16 row groups
        int cb = bid * CHUNK;
        int lim = min(cb + CHUNK, NN);
        float4 s = make_float4(0.f, 0.f, 0.f, 0.f);
        float4 s2 = make_float4(0.f, 0.f, 0.f, 0.f);
        for (int r = cb + rg; r < lim; r += 16) {
            uint2 hh = *(const uint2*)(g_h1h + (size_t)r * D + q * 4);
            uint2 ll = *(const uint2*)(g_h1l + (size_t)r * D + q * 4);
            float4 v = rec4(hh, ll);
            s.x += v.x; s.y += v.y; s.z += v.z; s.w += v.w;
            s2.x += v.x * v.x; s2.y += v.y * v.y;
            s2.z += v.z * v.z; s2.w += v.w * v.w;
        }
        __syncthreads();
        smf[rg * 32 + q] = s;
        smf[512 + rg * 32 + q] = s2;
        __syncthreads();
        if (tid < 32) {
            float4 ts = make_float4(0.f, 0.f, 0.f, 0.f);
            float4 t2 = make_float4(0.f, 0.f, 0.f, 0.f);
            for (int g = 0; g < 16; g++) {
                float4 a = smf[g * 32 + tid];
                float4 b = smf[512 + g * 32 + tid];
                ts.x += a.x; ts.y += a.y; ts.z += a.z; ts.w += a.w;
                t2.x += b.x; t2.y += b.y; t2.z += b.z; t2.w += b.w;
            }
            *(float4*)(g_ps + bid * D + tid * 4) = ts;
            *(float4*)(g_ps2 + bid * D + tid * 4) = t2;
        }
    }
    gbar();

    // ---- batchnorm finalize (replicated) + apply + relu ----
    {
        __shared__ float s_scale[D], s_shift[D];
        __shared__ float r1[NT], r2[NT];
        int col = tid & 127;
        int part = tid >> 7;
        float s = 0.f, s2 = 0.f;
        for (int b = part; b < NB; b += 4) {
            s += g_ps[b * D + col];
            s2 += g_ps2[b * D + col];
        }
        r1[tid] = s; r2[tid] = s2;
        __syncthreads();
        if (part == 0) {
            double S = (double)r1[col] + (double)r1[col + 128] +
                       (double)r1[col + 256] + (double)r1[col + 384];
            double S2 = (double)r2[col] + (double)r2[col + 128] +
                        (double)r2[col + 256] + (double)r2[col + 384];
            double mu = S / (double)NN;
            double var = S2 / (double)NN - mu * mu;
            float inv = rsqrtf((float)var + 1e-5f);
            float sc = inv * gamma[col];
            s_scale[col] = sc;
            s_shift[col] = beta[col] - (float)mu * sc;
        }
        __syncthreads();
        for (int i = gt; i < NN * 32; i += GS) {
            uint2 hh = ((const uint2*)g_h1h)[i];
            uint2 ll = ((const uint2*)g_h1l)[i];
            float4 v = rec4(hh, ll);
            int c = (i & 31) * 4;
            v.x = fmaxf(fmaf(v.x, s_scale[c + 0], s_shift[c + 0]), 0.f);
            v.y = fmaxf(fmaf(v.y, s_scale[c + 1], s_shift[c + 1]), 0.f);
            v.z = fmaxf(fmaf(v.z, s_scale[c + 2], s_shift[c + 2]), 0.f);
            v.w = fmaxf(fmaf(v.w, s_scale[c + 3], s_shift[c + 3]), 0.f);
            uint2 nh, nl;
            split4(v, nh, nl);
            ((uint2*)g_h1h)[i] = nh;
            ((uint2*)g_h1l)[i] = nl;
            ((uint2*)g_h116)[i] = half4(v);
        }
    }
    gbar();

    // ---- layer 2 ----
    agg_phase(g_h116);
    gbar();
    gemm_wmma<2>(g_mh, g_ml, g_h1h, g_h1l, Wl2, Wr2, bl2,
                 out, nullptr, nullptr, nullptr, base);
}

// -------- launch --------
extern "C" void kernel_launch(void* const* d_in, const int* in_sizes, int n_in,
                              void* d_out, int out_size) {
    const float* x     = (const float*)d_in[0];
    const int*   ei    = (const int*)d_in[1];
    const float* Wl0   = (const float*)d_in[2];
    const float* bl0   = (const float*)d_in[3];
    const float* Wr0   = (const float*)d_in[4];
    const float* Wl1   = (const float*)d_in[5];
    const float* bl1   = (const float*)d_in[6];
    const float* Wr1   = (const float*)d_in[7];
    const float* Wl2   = (const float*)d_in[8];
    const float* bl2   = (const float*)d_in[9];
    const float* Wr2   = (const float*)d_in[10];
    const float* gamma = (const float*)d_in[11];
    const float* beta  = (const float*)d_in[12];
    float* out = (float*)d_out;

    const int* srcp = ei;
    const int* dstp = ei + NE;

    const int SMEM = 6 * BUF_BYTES + 1024;  // 209920
    static bool attr_set = false;
    if (!attr_set) {
        cudaFuncSetAttribute(mono_kernel,
                             cudaFuncAttributeMaxDynamicSharedMemorySize, SMEM);
        attr_set = true;
    }

    mono_kernel<<<NB, NT, SMEM>>>(x, srcp, dstp,
                                  Wl0, bl0, Wr0,
                                  Wl1, bl1, Wr1,
                                  Wl2, bl2, Wr2,
                                  gamma, beta, out);
}

// round 10
// speedup vs baseline: 17.9132x; 1.0065x over previous
#include <cuda_runtime.h>
#include <cuda_bf16.h>
#include <cuda_fp16.h>
#include <mma.h>
#include <cstdint>

using namespace nvcuda;

#define NN 50000
#define NE 800000
#define D 128
#define NB 148
#define NT 1024
#define GS (NB * NT)
#define NWARPS (NT / 32)             // 32
#define CHUNK ((NN + NB - 1) / NB)   // 338 nodes per block
#define NTILES ((NN + 127) / 128)    // 391
#define LDA 136                       // bf16 smem leading dim (padded)
#define LDS_ 132                      // f32 staging leading dim (padded)
#define BUF_BYTES (128 * LDA * 2)     // 34816 bytes per bf16 smem buffer

typedef unsigned long long u64;

// -------- device scratch (no runtime allocation allowed) --------
__device__ unsigned g_gen = 0;
__device__ unsigned g_arrive = 0;
__device__ int   g_cnt[NN];
__device__ int   g_off[NN + 1];
__device__ int   g_pos[NN];
__device__ int   g_srcs[NE];
__device__ int   g_bsum[NB];
__device__ float g_ps[NB * D];
__device__ float g_ps2[NB * D];
// split-bf16 + fp16 feature buffers
__device__ __nv_bfloat16 g_xh[NN * D];
__device__ __nv_bfloat16 g_xl[NN * D];
__device__ __half        g_x16[NN * D];
__device__ __nv_bfloat16 g_mh[NN * D];
__device__ __nv_bfloat16 g_ml[NN * D];
__device__ __nv_bfloat16 g_h0h[NN * D];
__device__ __nv_bfloat16 g_h0l[NN * D];
__device__ __half        g_h016[NN * D];
__device__ __nv_bfloat16 g_h1h[NN * D];
__device__ __nv_bfloat16 g_h1l[NN * D];
__device__ __half        g_h116[NN * D];

// -------- helpers --------
__device__ __forceinline__ uint32_t cvt2(float lo, float hi) {
    uint32_t r;
    asm("cvt.rn.bf16x2.f32 %0, %1, %2;" : "=r"(r) : "f"(hi), "f"(lo));
    return r;
}
__device__ __forceinline__ void split4(float4 v, uint2& h, uint2& l) {
    uint32_t h0 = cvt2(v.x, v.y);
    uint32_t h1 = cvt2(v.z, v.w);
    uint32_t l0 = cvt2(v.x - __uint_as_float(h0 << 16),
                       v.y - __uint_as_float(h0 & 0xffff0000u));
    uint32_t l1 = cvt2(v.z - __uint_as_float(h1 << 16),
                       v.w - __uint_as_float(h1 & 0xffff0000u));
    h = make_uint2(h0, h1);
    l = make_uint2(l0, l1);
}
__device__ __forceinline__ uint2 half4(float4 v) {
    uint2 r;
    *(__half2*)&r.x = __floats2half2_rn(v.x, v.y);
    *(__half2*)&r.y = __floats2half2_rn(v.z, v.w);
    return r;
}
__device__ __forceinline__ float4 rec4(uint2 h, uint2 l) {
    float4 v;
    v.x = __uint_as_float(h.x << 16) + __uint_as_float(l.x << 16);
    v.y = __uint_as_float(h.x & 0xffff0000u) + __uint_as_float(l.x & 0xffff0000u);
    v.z = __uint_as_float(h.y << 16) + __uint_as_float(l.y << 16);
    v.w = __uint_as_float(h.y & 0xffff0000u) + __uint_as_float(l.y & 0xffff0000u);
    return v;
}

// -------- grid-wide software barrier --------
__device__ __forceinline__ void gbar() {
    __syncthreads();
    if (threadIdx.x == 0) {
        __threadfence();
        unsigned gen = atomicAdd(&g_gen, 0u);
        unsigned arrived = atomicAdd(&g_arrive, 1u) + 1u;
        if (arrived == NB) {
            atomicExch(&g_arrive, 0u);
            __threadfence();
            atomicAdd(&g_gen, 1u);
        } else {
            while (atomicAdd(&g_gen, 0u) == gen) { __nanosleep(128); }
        }
        __threadfence();
    }
    __syncthreads();
}

// -------- mean aggregation: fp16 gather, split-bf16 mean output --------
__device__ __forceinline__ void agg_phase(const __half* __restrict__ h16) {
    const int lane = threadIdx.x & 31;
    const int warp = threadIdx.x >> 5;
    const int gw0 = blockIdx.x * NWARPS + warp;
    for (int n = gw0; n < NN; n += NB * NWARPS) {
        int beg = g_off[n];
        int end = g_off[n + 1];
        float4 a0 = make_float4(0.f, 0.f, 0.f, 0.f);
        float4 a1 = make_float4(0.f, 0.f, 0.f, 0.f);
        int i = beg;
        for (; i + 7 < end; i += 8) {
            int s0 = __ldg(&g_srcs[i]);
            int s1 = __ldg(&g_srcs[i + 1]);
            int s2 = __ldg(&g_srcs[i + 2]);
            int s3 = __ldg(&g_srcs[i + 3]);
            int s4 = __ldg(&g_srcs[i + 4]);
            int s5 = __ldg(&g_srcs[i + 5]);
            int s6 = __ldg(&g_srcs[i + 6]);
            int s7 = __ldg(&g_srcs[i + 7]);
            uint2 u0 = __ldg((const uint2*)(h16 + (size_t)s0 * D + lane * 4));
            uint2 u1 = __ldg((const uint2*)(h16 + (size_t)s1 * D + lane * 4));
            uint2 u2 = __ldg((const uint2*)(h16 + (size_t)s2 * D + lane * 4));
            uint2 u3 = __ldg((const uint2*)(h16 + (size_t)s3 * D + lane * 4));
            uint2 u4 = __ldg((const uint2*)(h16 + (size_t)s4 * D + lane * 4));
            uint2 u5 = __ldg((const uint2*)(h16 + (size_t)s5 * D + lane * 4));
            uint2 u6 = __ldg((const uint2*)(h16 + (size_t)s6 * D + lane * 4));
            uint2 u7 = __ldg((const uint2*)(h16 + (size_t)s7 * D + lane * 4));
#define ACC(acc, u) do { \
            float2 p = __half22float2(*(const __half2*)&(u).x); \
            float2 q = __half22float2(*(const __half2*)&(u).y); \
            (acc).x += p.x; (acc).y += p.y; (acc).z += q.x; (acc).w += q.y; } while (0)
            ACC(a0, u0); ACC(a0, u1); ACC(a0, u2); ACC(a0, u3);
            ACC(a1, u4); ACC(a1, u5); ACC(a1, u6); ACC(a1, u7);
        }
        for (; i < end; i++) {
            int s0 = __ldg(&g_srcs[i]);
            uint2 u0 = __ldg((const uint2*)(h16 + (size_t)s0 * D + lane * 4));
            ACC(a0, u0);
        }
#undef ACC
        float inv = 1.0f / fmaxf((float)(end - beg), 1.0f);
        float4 r;
        r.x = (a0.x + a1.x) * inv;
        r.y = (a0.y + a1.y) * inv;
        r.z = (a0.z + a1.z) * inv;
        r.w = (a0.w + a1.w) * inv;
        uint2 hh, ll;
        split4(r, hh, ll);
        *(uint2*)(g_mh + (size_t)n * D + lane * 4) = hh;
        *(uint2*)(g_ml + (size_t)n * D + lane * 4) = ll;
    }
}

// -------- fp32 W -> split bf16 smem (padded), once per GEMM call --------
__device__ __forceinline__ void conv_w(const float* __restrict__ S,
                                       __nv_bfloat16* __restrict__ dhi,
                                       __nv_bfloat16* __restrict__ dlo) {
#pragma unroll
    for (int it = 0; it < 4; it++) {
        int idx = threadIdx.x + it * NT;     // 0..4095 quads
        int r = idx >> 5;
        int kq = idx & 31;
        float4 v = *(const float4*)(S + (size_t)r * D + kq * 4);
        uint2 h, l;
        split4(v, h, l);
        int off = r * LDA + kq * 4;
        *(uint2*)(dhi + off) = h;
        *(uint2*)(dlo + off) = l;
    }
}

// -------- tensor-core fused dual GEMM, pre-split A from gmem ----
// 32 warps: warp grid 8 rows x 4 cols; warp tile 16 rows x 32 cols (2 frags).
// MODE 0: relu -> (oh,ol,o16).  MODE 1: -> (oh,ol).  MODE 2: -> fp32 outf.
template <int MODE>
__device__ __forceinline__ void gemm_wmma(
    const __nv_bfloat16* __restrict__ a0h, const __nv_bfloat16* __restrict__ a0l,
    const __nv_bfloat16* __restrict__ a1h, const __nv_bfloat16* __restrict__ a1l,
    const float* __restrict__ Wl, const float* __restrict__ Wr,
    const float* __restrict__ bias,
    float* __restrict__ outf,
    __nv_bfloat16* __restrict__ oh, __nv_bfloat16* __restrict__ ol,
    __half* __restrict__ o16, char* base) {
    __nv_bfloat16* wlh = (__nv_bfloat16*)(base);
    __nv_bfloat16* wll = (__nv_bfloat16*)(base + BUF_BYTES);
    __nv_bfloat16* wrh = (__nv_bfloat16*)(base + 2 * BUF_BYTES);
    __nv_bfloat16* wrl = (__nv_bfloat16*)(base + 3 * BUF_BYTES);
    __nv_bfloat16* ahi = (__nv_bfloat16*)(base + 4 * BUF_BYTES);
    __nv_bfloat16* alo = (__nv_bfloat16*)(base + 5 * BUF_BYTES);
    float* staging = (float*)(base + 4 * BUF_BYTES);  // reuses ahi+alo

    const int tid = threadIdx.x;
    const int warp = tid >> 5;
    const int wr_ = warp >> 2;   // 0..7 -> rows wr_*16
    const int wc_ = warp & 3;    // 0..3 -> cols wc_*32

    conv_w(Wl, wlh, wll);
    conv_w(Wr, wrh, wrl);
    __syncthreads();

    for (int t = blockIdx.x; t < NTILES; t += NB) {
        const int row0 = t * 128;

        wmma::fragment<wmma::accumulator, 16, 16, 16, float> fc[2];
#pragma unroll
        for (int j = 0; j < 2; j++) wmma::fill_fragment(fc[j], 0.f);

#pragma unroll
        for (int ph = 0; ph < 2; ph++) {
            const __nv_bfloat16* Ah = ph ? a1h : a0h;
            const __nv_bfloat16* Al = ph ? a1l : a0l;
            // copy pre-split tile into padded smem (16B granules)
#pragma unroll
            for (int it = 0; it < 2; it++) {
                int idx = tid + it * NT;      // 0..2047
                int r = idx >> 4;
                int g = idx & 15;
                int row = row0 + r;
                uint4 vh = make_uint4(0, 0, 0, 0), vl = make_uint4(0, 0, 0, 0);
                if (row < NN) {
                    vh = __ldg((const uint4*)(Ah + (size_t)row * D + g * 8));
                    vl = __ldg((const uint4*)(Al + (size_t)row * D + g * 8));
                }
                *(uint4*)(ahi + r * LDA + g * 8) = vh;
                *(uint4*)(alo + r * LDA + g * 8) = vl;
            }
            __syncthreads();
            const __nv_bfloat16* wh = ph ? wrh : wlh;
            const __nv_bfloat16* wl = ph ? wrl : wll;

#pragma unroll
            for (int ks = 0; ks < 8; ks++) {
                wmma::fragment<wmma::matrix_a, 16, 16, 16, __nv_bfloat16,
                               wmma::row_major> fa_hi, fa_lo;
                const int r = wr_ * 16;
                wmma::load_matrix_sync(fa_hi, ahi + r * LDA + ks * 16, LDA);
                wmma::load_matrix_sync(fa_lo, alo + r * LDA + ks * 16, LDA);
#pragma unroll
                for (int j = 0; j < 2; j++) {
                    wmma::fragment<wmma::matrix_b, 16, 16, 16, __nv_bfloat16,
                                   wmma::col_major> fb_hi, fb_lo;
                    const int c = wc_ * 32 + j * 16;
                    wmma::load_matrix_sync(fb_hi, wh + c * LDA + ks * 16, LDA);
                    wmma::load_matrix_sync(fb_lo, wl + c * LDA + ks * 16, LDA);
                    wmma::mma_sync(fc[j], fa_hi, fb_hi, fc[j]);
                    wmma::mma_sync(fc[j], fa_hi, fb_lo, fc[j]);
                    wmma::mma_sync(fc[j], fa_lo, fb_hi, fc[j]);
                }
            }
            __syncthreads();
        }

        // stage accumulators to smem (reuses ahi/alo area)
#pragma unroll
        for (int j = 0; j < 2; j++)
            wmma::store_matrix_sync(
                staging + (wr_ * 16) * LDS_ + wc_ * 32 + j * 16,
                fc[j], LDS_, wmma::mem_row_major);
        __syncthreads();

        // epilogue
#pragma unroll
        for (int it = 0; it < 4; it++) {
            int idx = tid + it * NT;    // 0..4095 float4 slots
            int r = idx >> 5;
            int cq = idx & 31;
            int row = row0 + r;
            if (row < NN) {
                float4 v = *(const float4*)(staging + r * LDS_ + cq * 4);
                float4 b4 = *(const float4*)(bias + cq * 4);
                v.x += b4.x; v.y += b4.y; v.z += b4.z; v.w += b4.w;
                size_t off = (size_t)row * D + cq * 4;
                if (MODE == 0) {
                    v.x = fmaxf(v.x, 0.f); v.y = fmaxf(v.y, 0.f);
                    v.z = fmaxf(v.z, 0.f); v.w = fmaxf(v.w, 0.f);
                    uint2 hh, ll;
                    split4(v, hh, ll);
                    *(uint2*)(oh + off) = hh;
                    *(uint2*)(ol + off) = ll;
                    *(uint2*)(o16 + off) = half4(v);
                } else if (MODE == 1) {
                    uint2 hh, ll;
                    split4(v, hh, ll);
                    *(uint2*)(oh + off) = hh;
                    *(uint2*)(ol + off) = ll;
                } else {
                    *(float4*)(outf + off) = v;
                }
            }
        }
        __syncthreads();
    }
}

// -------- the mono-kernel --------
__global__ void __launch_bounds__(NT, 1)
mono_kernel(const float* __restrict__ x,
            const int* __restrict__ src, const int* __restrict__ dst,
            const float* __restrict__ Wl0, const float* __restrict__ bl0,
            const float* __restrict__ Wr0,
            const float* __restrict__ Wl1, const float* __restrict__ bl1,
            const float* __restrict__ Wr1,
            const float* __restrict__ Wl2, const float* __restrict__ bl2,
            const float* __restrict__ Wr2,
            const float* __restrict__ gamma, const float* __restrict__ beta,
            float* __restrict__ out) {
    extern __shared__ char smc[];
    char* base = (char*)(((uintptr_t)smc + 1023) & ~(uintptr_t)1023);
    const int tid = threadIdx.x;
    const int bid = blockIdx.x;
    const int gt = bid * NT + tid;
    const int lane = tid & 31;
    const int warp = tid >> 5;

    // ---- phase 1: histogram of dst + split/convert x ----
    for (int e = gt; e < NE; e += GS) atomicAdd(&g_cnt[dst[e]], 1);
    for (int i = gt; i < NN * 32; i += GS) {
        float4 v = __ldg((const float4*)(x + (size_t)i * 4));
        uint2 h, l;
        split4(v, h, l);
        ((uint2*)g_xh)[i] = h;
        ((uint2*)g_xl)[i] = l;
        ((uint2*)g_x16)[i] = half4(v);
    }
    gbar();

    // ---- phase 2: per-block chunk sums ----
    {
        __shared__ int red[NWARPS];
        int cb = bid * CHUNK;
        int v = 0;
        for (int i = tid; i < CHUNK; i += NT) {
            int idx = cb + i;
            if (idx < NN) v += g_cnt[idx];
        }
#pragma unroll
        for (int o = 16; o > 0; o >>= 1) v += __shfl_down_sync(0xffffffffu, v, o);
        if (lane == 0) red[warp] = v;
        __syncthreads();
        if (warp == 0) {
            int w = (lane < NWARPS) ? red[lane] : 0;
#pragma unroll
            for (int o = 16; o > 0; o >>= 1) w += __shfl_down_sync(0xffffffffu, w, o);
            if (lane == 0) g_bsum[bid] = w;
        }
    }
    gbar();

    // ---- phase 3: every block scans block sums locally ----
    __shared__ int s_boff;
    {
        __shared__ int sb[NB];
        if (tid < NB) sb[tid] = g_bsum[tid];
        __syncthreads();
        if (tid == 0) {
            int run = 0;
            for (int b = 0; b < NB; b++) { int v = sb[b]; sb[b] = run; run += v; }
            s_boff = sb[bid];
        }
        __syncthreads();
        if (bid == NB - 1 && tid == 0) g_off[NN] = NE;
    }

    // ---- phase 4: write offsets, reset g_cnt ----
    {
        __shared__ int wsum[NWARPS];
        int cb = bid * CHUNK;
        int idx = cb + tid;
        int v = (tid < CHUNK && idx < NN) ? g_cnt[idx] : 0;
        int inc = v;
#pragma unroll
        for (int o = 1; o < 32; o <<= 1) {
            int u = __shfl_up_sync(0xffffffffu, inc, o);
            if (lane >= o) inc += u;
        }
        if (lane == 31) wsum[warp] = inc;
        __syncthreads();
        if (warp == 0) {
            int w = (lane < NWARPS) ? wsum[lane] : 0;
            int wi = w;
#pragma unroll
            for (int o = 1; o < NWARPS; o <<= 1) {
                int u = __shfl_up_sync(0xffffffffu, wi, o);
                if (lane >= o) wi += u;
            }
            if (lane < NWARPS) wsum[lane] = wi - w;
        }
        __syncthreads();
        int excl = s_boff + wsum[warp] + inc - v;
        if (tid < CHUNK && idx < NN) {
            g_off[idx] = excl;
            g_pos[idx] = excl;
            g_cnt[idx] = 0;
        }
    }
    gbar();

    // ---- phase 5: scatter src by dst ----
    for (int e = gt; e < NE; e += GS) {
        int p = atomicAdd(&g_pos[dst[e]], 1);
        g_srcs[p] = src[e];
    }
    gbar();

    // ---- layer 0 ----
    agg_phase(g_x16);
    gbar();
    gemm_wmma<0>(g_mh, g_ml, g_xh, g_xl, Wl0, Wr0, bl0,
                 nullptr, g_h0h, g_h0l, g_h016, base);
    gbar();

    // ---- layer 1 ----
    agg_phase(g_h016);
    gbar();
    gemm_wmma<1>(g_mh, g_ml, g_h0h, g_h0l, Wl1, Wr1, bl1,
                 nullptr, g_h1h, g_h1l, nullptr, base);
    gbar();

    // ---- batchnorm stats ----
    {
        float4* smf = (float4*)base;
        int q = tid & 31;
        int rg = tid >> 5;  // 32 row groups
        int cb = bid * CHUNK;
        int lim = min(cb + CHUNK, NN);
        float4 s = make_float4(0.f, 0.f, 0.f, 0.f);
        float4 s2 = make_float4(0.f, 0.f, 0.f, 0.f);
        for (int r = cb + rg; r < lim; r += 32) {
            uint2 hh = *(const uint2*)(g_h1h + (size_t)r * D + q * 4);
            uint2 ll = *(const uint2*)(g_h1l + (size_t)r * D + q * 4);
            float4 v = rec4(hh, ll);
            s.x += v.x; s.y += v.y; s.z += v.z; s.w += v.w;
            s2.x += v.x * v.x; s2.y += v.y * v.y;
            s2.z += v.z * v.z; s2.w += v.w * v.w;
        }
        __syncthreads();
        smf[rg * 32 + q] = s;
        smf[1024 + rg * 32 + q] = s2;
        __syncthreads();
        if (tid < 32) {
            float4 ts = make_float4(0.f, 0.f, 0.f, 0.f);
            float4 t2 = make_float4(0.f, 0.f, 0.f, 0.f);
            for (int g = 0; g < 32; g++) {
                float4 a = smf[g * 32 + tid];
                float4 b = smf[1024 + g * 32 + tid];
                ts.x += a.x; ts.y += a.y; ts.z += a.z; ts.w += a.w;
                t2.x += b.x; t2.y += b.y; t2.z += b.z; t2.w += b.w;
            }
            *(float4*)(g_ps + bid * D + tid * 4) = ts;
            *(float4*)(g_ps2 + bid * D + tid * 4) = t2;
        }
    }
    gbar();

    // ---- batchnorm finalize (replicated) + apply + relu ----
    {
        __shared__ float s_scale[D], s_shift[D];
        __shared__ float r1[NT], r2[NT];
        int col = tid & 127;
        int part = tid >> 7;  // 0..7
        float s = 0.f, s2 = 0.f;
        for (int b = part; b < NB; b += 8) {
            s += g_ps[b * D + col];
            s2 += g_ps2[b * D + col];
        }
        r1[tid] = s; r2[tid] = s2;
        __syncthreads();
        if (part == 0) {
            double S = 0.0, S2 = 0.0;
#pragma unroll
            for (int p = 0; p < 8; p++) {
                S += (double)r1[col + p * 128];
                S2 += (double)r2[col + p * 128];
            }
            double mu = S / (double)NN;
            double var = S2 / (double)NN - mu * mu;
            float inv = rsqrtf((float)var + 1e-5f);
            float sc = inv * gamma[col];
            s_scale[col] = sc;
            s_shift[col] = beta[col] - (float)mu * sc;
        }
        __syncthreads();
        for (int i = gt; i < NN * 32; i += GS) {
            uint2 hh = ((const uint2*)g_h1h)[i];
            uint2 ll = ((const uint2*)g_h1l)[i];
            float4 v = rec4(hh, ll);
            int c = (i & 31) * 4;
            v.x = fmaxf(fmaf(v.x, s_scale[c + 0], s_shift[c + 0]), 0.f);
            v.y = fmaxf(fmaf(v.y, s_scale[c + 1], s_shift[c + 1]), 0.f);
            v.z = fmaxf(fmaf(v.z, s_scale[c + 2], s_shift[c + 2]), 0.f);
            v.w = fmaxf(fmaf(v.w, s_scale[c + 3], s_shift[c + 3]), 0.f);
            uint2 nh, nl;
            split4(v, nh, nl);
            ((uint2*)g_h1h)[i] = nh;
            ((uint2*)g_h1l)[i] = nl;
            ((uint2*)g_h116)[i] = half4(v);
        }
    }
    gbar();

    // ---- layer 2 ----
    agg_phase(g_h116);
    gbar();
    gemm_wmma<2>(g_mh, g_ml, g_h1h, g_h1l, Wl2, Wr2, bl2,
                 out, nullptr, nullptr, nullptr, base);
}

// -------- launch --------
extern "C" void kernel_launch(void* const* d_in, const int* in_sizes, int n_in,
                              void* d_out, int out_size) {
    const float* x     = (const float*)d_in[0];
    const int*   ei    = (const int*)d_in[1];
    const float* Wl0   = (const float*)d_in[2];
    const float* bl0   = (const float*)d_in[3];
    const float* Wr0   = (const float*)d_in[4];
    const float* Wl1   = (const float*)d_in[5];
    const float* bl1   = (const float*)d_in[6];
    const float* Wr1   = (const float*)d_in[7];
    const float* Wl2   = (const float*)d_in[8];
    const float* bl2   = (const float*)d_in[9];
    const float* Wr2   = (const float*)d_in[10];
    const float* gamma = (const float*)d_in[11];
    const float* beta  = (const float*)d_in[12];
    float* out = (float*)d_out;

    const int* srcp = ei;
    const int* dstp = ei + NE;

    const int SMEM = 6 * BUF_BYTES + 1024;  // 209920
    static bool attr_set = false;
    if (!attr_set) {
        cudaFuncSetAttribute(mono_kernel,
                             cudaFuncAttributeMaxDynamicSharedMemorySize, SMEM);
        attr_set = true;
    }

    mono_kernel<<<NB, NT, SMEM>>>(x, srcp, dstp,
                                  Wl0, bl0, Wr0,
                                  Wl1, bl1, Wr1,
                                  Wl2, bl2, Wr2,
                                  gamma, beta, out);
}